// round 5
// baseline (speedup 1.0000x reference)
#include <cuda_runtime.h>
#include <cuda_bf16.h>
#include <math.h>

// Problem constants (B=1, L=4096, DM=1024, NH=16, DH=64, w=512, C=8)
#define L_TOK   4096
#define DMODEL  1024
#define NHEAD   16
#define DHEAD   64
#define WCHUNK  512
#define NCHUNK  8
#define NKEY    (3 * WCHUNK)        // 1536 effective keys
#define NQROW   (L_TOK * NHEAD)     // 65536 query rows of dim 64

// -------------------- scratch (no cudaMalloc allowed) --------------------
__device__ float g_qp [L_TOK * DMODEL];       // 16 MB
__device__ float g_kvp[L_TOK * 2 * DHEAD];    // 2 MB
__device__ float g_keff[NKEY * DHEAD];        // 384 KB
__device__ float g_veff[NKEY * DHEAD];        // 384 KB
__device__ float g_ctx[L_TOK * DMODEL];       // 16 MB

// -------------------- generic tiled SGEMM: C = alpha * A(MxK) * B(KxN) ----
// BM=BN=128, BK=8, 256 threads, 8x8 microtile. M,N,K multiples of tiles.
__global__ __launch_bounds__(256) void sgemm128(
    const float* __restrict__ A, const float* __restrict__ B,
    float* __restrict__ C, int M, int N, int K, float alpha)
{
    __shared__ float As[8][128];
    __shared__ float Bs[8][128];

    const int tid = threadIdx.x;
    const int bm = blockIdx.y * 128;
    const int bn = blockIdx.x * 128;
    const int tr = tid >> 4;          // 0..15
    const int tc = tid & 15;          // 0..15

    // A loader: thread -> (row = tid/2, kcol = (tid&1)*4), float4 along K
    const int arow = tid >> 1;
    const int acol = (tid & 1) * 4;
    // B loader: thread -> (krow = tid/32, col = (tid&31)*4), float4 along N
    const int brow = tid >> 5;
    const int bcol = (tid & 31) * 4;

    const float* Aptr = A + (size_t)(bm + arow) * K + acol;
    const float* Bptr = B + (size_t)brow * N + bn + bcol;

    float acc[8][8];
#pragma unroll
    for (int i = 0; i < 8; i++)
#pragma unroll
        for (int j = 0; j < 8; j++) acc[i][j] = 0.f;

    for (int k0 = 0; k0 < K; k0 += 8) {
        float4 av = *(const float4*)(Aptr + k0);
        float4 bv = *(const float4*)(Bptr + (size_t)k0 * N);
        __syncthreads();                 // previous tile's compute done
        As[acol + 0][arow] = av.x;
        As[acol + 1][arow] = av.y;
        As[acol + 2][arow] = av.z;
        As[acol + 3][arow] = av.w;
        *(float4*)&Bs[brow][bcol] = bv;
        __syncthreads();

#pragma unroll
        for (int kk = 0; kk < 8; ++kk) {
            float a[8], b[8];
            *(float4*)(a)     = *(const float4*)&As[kk][tr * 8];
            *(float4*)(a + 4) = *(const float4*)&As[kk][tr * 8 + 4];
            *(float4*)(b)     = *(const float4*)&Bs[kk][tc * 8];
            *(float4*)(b + 4) = *(const float4*)&Bs[kk][tc * 8 + 4];
#pragma unroll
            for (int i = 0; i < 8; i++)
#pragma unroll
                for (int j = 0; j < 8; j++)
                    acc[i][j] += a[i] * b[j];
        }
    }

#pragma unroll
    for (int i = 0; i < 8; i++) {
        float* crow = C + (size_t)(bm + tr * 8 + i) * N + bn + tc * 8;
#pragma unroll
        for (int j4 = 0; j4 < 2; j4++) {
            float4 v;
            v.x = alpha * acc[i][j4 * 4 + 0];
            v.y = alpha * acc[i][j4 * 4 + 1];
            v.z = alpha * acc[i][j4 * 4 + 2];
            v.w = alpha * acc[i][j4 * 4 + 3];
            *(float4*)(crow + j4 * 4) = v;
        }
    }
}

// -------------------- build K_eff / V_eff from kvp chunk sums -------------
__global__ void build_eff(const float* __restrict__ kvp,
                          float* __restrict__ keff, float* __restrict__ veff)
{
    int idx = blockIdx.x * blockDim.x + threadIdx.x;   // 0..512*64-1
    if (idx >= WCHUNK * DHEAD) return;
    int y = idx >> 6;
    int d = idx & 63;

    float ks = 0.f, vs = 0.f, kf = 0.f, vf = 0.f, kl = 0.f, vl = 0.f;
#pragma unroll
    for (int c = 0; c < NCHUNK; c++) {
        const float* row = kvp + (size_t)((c << 9) + y) * (2 * DHEAD);
        float kx = row[d];
        float vx = row[DHEAD + d];
        if (c == 0)          { kf = kx; vf = vx; }
        if (c == NCHUNK - 1) { kl = kx; vl = vx; }
        ks += kx; vs += vx;
    }
    // e=0: all chunks except last; e=1: all; e=2: all except first
    keff[(0 * WCHUNK + y) * DHEAD + d] = ks - kl;
    keff[(1 * WCHUNK + y) * DHEAD + d] = ks;
    keff[(2 * WCHUNK + y) * DHEAD + d] = ks - kf;
    veff[(0 * WCHUNK + y) * DHEAD + d] = vs - vl;
    veff[(1 * WCHUNK + y) * DHEAD + d] = vs;
    veff[(2 * WCHUNK + y) * DHEAD + d] = vs - vf;
}

// -------------------- fused attention: softmax(Q K^T) V -------------------
// Q:[65536,64] (== qp reinterpreted), K,V:[1536,64] shared by all queries.
// Block: 256 threads, 64 query rows, key tiles of 64. Online softmax.
// Smem: Qs | KPs (K tile reused as P tile) | Vs, stride 68 floats.
#define AT_STRIDE 68
#define AT_SMEM_BYTES (3 * 64 * AT_STRIDE * 4)

__global__ __launch_bounds__(256) void attn_kernel(
    const float* __restrict__ Q, const float* __restrict__ Keff,
    const float* __restrict__ Veff, float* __restrict__ O)
{
    extern __shared__ float sm[];
    float* Qs  = sm;                       // [64][68]
    float* KPs = sm + 64 * AT_STRIDE;      // [64][68]  K tile, then P tile
    float* Vs  = sm + 2 * 64 * AT_STRIDE;  // [64][68]

    const int tid = threadIdx.x;
    const int ty = tid >> 4;     // 0..15 -> query rows ty*4..+3
    const int tx = tid & 15;     // 0..15 -> key cols / out dims tx*4..+3
    const int qbase = blockIdx.x * 64;

    // load Q tile (64x64)
    for (int i = tid; i < 64 * 16; i += 256) {
        int r = i >> 4, c4 = (i & 15) * 4;
        float4 v = *(const float4*)&Q[(size_t)(qbase + r) * 64 + c4];
        *(float4*)&Qs[r * AT_STRIDE + c4] = v;
    }

    float m[4], l[4], o[4][4];
#pragma unroll
    for (int i = 0; i < 4; i++) {
        m[i] = -1e30f; l[i] = 0.f;
#pragma unroll
        for (int j = 0; j < 4; j++) o[i][j] = 0.f;
    }

    for (int kt = 0; kt < NKEY / 64; ++kt) {
        __syncthreads();   // previous PV stage done reading KPs/Vs
        const int kbase = kt * 64;
        for (int i = tid; i < 64 * 16; i += 256) {
            int r = i >> 4, c4 = (i & 15) * 4;
            *(float4*)&KPs[r * AT_STRIDE + c4] =
                *(const float4*)&Keff[(size_t)(kbase + r) * 64 + c4];
            *(float4*)&Vs[r * AT_STRIDE + c4] =
                *(const float4*)&Veff[(size_t)(kbase + r) * 64 + c4];
        }
        __syncthreads();

        // S = Q K^T, 4x4 microtile
        float s[4][4];
#pragma unroll
        for (int i = 0; i < 4; i++)
#pragma unroll
            for (int j = 0; j < 4; j++) s[i][j] = 0.f;

#pragma unroll
        for (int d0 = 0; d0 < 64; d0 += 4) {
            float4 a[4], b[4];
#pragma unroll
            for (int i = 0; i < 4; i++)
                a[i] = *(const float4*)&Qs[(ty * 4 + i) * AT_STRIDE + d0];
#pragma unroll
            for (int j = 0; j < 4; j++)
                b[j] = *(const float4*)&KPs[(tx * 4 + j) * AT_STRIDE + d0];
#pragma unroll
            for (int i = 0; i < 4; i++)
#pragma unroll
                for (int j = 0; j < 4; j++)
                    s[i][j] += a[i].x * b[j].x + a[i].y * b[j].y +
                               a[i].z * b[j].z + a[i].w * b[j].w;
        }

        // online softmax (m/l replicated across the 16 lanes sharing rows)
        float mnew[4], corr[4];
#pragma unroll
        for (int i = 0; i < 4; i++) {
            float rm = s[i][0];
            rm = fmaxf(rm, s[i][1]); rm = fmaxf(rm, s[i][2]); rm = fmaxf(rm, s[i][3]);
#pragma unroll
            for (int sh = 1; sh < 16; sh <<= 1)
                rm = fmaxf(rm, __shfl_xor_sync(0xffffffffu, rm, sh));
            mnew[i] = fmaxf(m[i], rm);
            corr[i] = __expf(m[i] - mnew[i]);
            m[i] = mnew[i];
        }
        float p[4][4];
#pragma unroll
        for (int i = 0; i < 4; i++) {
            float rs = 0.f;
#pragma unroll
            for (int j = 0; j < 4; j++) {
                p[i][j] = __expf(s[i][j] - mnew[i]);
                rs += p[i][j];
            }
#pragma unroll
            for (int sh = 1; sh < 16; sh <<= 1)
                rs += __shfl_xor_sync(0xffffffffu, rs, sh);
            l[i] = l[i] * corr[i] + rs;
#pragma unroll
            for (int j = 0; j < 4; j++) o[i][j] *= corr[i];
        }

        __syncthreads();   // done reading K tile -> reuse as P tile
#pragma unroll
        for (int i = 0; i < 4; i++)
            *(float4*)&KPs[(ty * 4 + i) * AT_STRIDE + tx * 4] = *(float4*)p[i];
        __syncthreads();

        // O += P V
#pragma unroll 4
        for (int c = 0; c < 64; ++c) {
            float4 vv = *(const float4*)&Vs[c * AT_STRIDE + tx * 4];
#pragma unroll
            for (int i = 0; i < 4; i++) {
                float pv = KPs[(ty * 4 + i) * AT_STRIDE + c];
                o[i][0] += pv * vv.x; o[i][1] += pv * vv.y;
                o[i][2] += pv * vv.z; o[i][3] += pv * vv.w;
            }
        }
    }

#pragma unroll
    for (int i = 0; i < 4; i++) {
        float inv = 1.f / l[i];
        float4 v;
        v.x = o[i][0] * inv; v.y = o[i][1] * inv;
        v.z = o[i][2] * inv; v.w = o[i][3] * inv;
        *(float4*)&O[(size_t)(qbase + ty * 4 + i) * 64 + tx * 4] = v;
    }
}

// -------------------- launch --------------------
extern "C" void kernel_launch(void* const* d_in, const int* in_sizes, int n_in,
                              void* d_out, int out_size)
{
    const float* q   = (const float*)d_in[0];
    const float* kv  = (const float*)d_in[1];
    const float* Wq  = (const float*)d_in[2];
    const float* Wkv = (const float*)d_in[3];
    const float* Wc  = (const float*)d_in[4];
    float* out = (float*)d_out;

    float *qp, *kvp, *keff, *veff, *ctx;
    cudaGetSymbolAddress((void**)&qp,   g_qp);
    cudaGetSymbolAddress((void**)&kvp,  g_kvp);
    cudaGetSymbolAddress((void**)&keff, g_keff);
    cudaGetSymbolAddress((void**)&veff, g_veff);
    cudaGetSymbolAddress((void**)&ctx,  g_ctx);

    cudaFuncSetAttribute(attn_kernel,
                         cudaFuncAttributeMaxDynamicSharedMemorySize,
                         AT_SMEM_BYTES);

    // kvp = kv @ Wkv  (4096 x 128 x 1024)
    sgemm128<<<dim3(1, 32), 256>>>(kv, Wkv, kvp, L_TOK, 2 * DHEAD, DMODEL, 1.0f);
    // K_eff / V_eff chunk sums
    build_eff<<<(WCHUNK * DHEAD + 255) / 256, 256>>>(kvp, keff, veff);
    // qp = (q @ Wq) / sqrt(dh)  (4096 x 1024 x 1024)
    sgemm128<<<dim3(8, 32), 256>>>(q, Wq, qp, L_TOK, DMODEL, DMODEL, 0.125f);
    // attention: Q[65536,64] vs shared K/V[1536,64]
    attn_kernel<<<NQROW / 64, 256, AT_SMEM_BYTES>>>(qp, keff, veff, ctx);
    // out = ctx @ Wc  (4096 x 1024 x 1024)
    sgemm128<<<dim3(8, 32), 256>>>(ctx, Wc, out, L_TOK, DMODEL, DMODEL, 1.0f);
}

// round 6
// speedup vs baseline: 3.6815x; 3.6815x over previous
#include <cuda_runtime.h>
#include <cuda_bf16.h>
#include <math.h>

// Problem constants (B=1, L=4096, DM=1024, NH=16, DH=64, w=512, C=8)
#define L_TOK   4096
#define DMODEL  1024
#define DHEAD   64
#define WCHUNK  512
#define NCHUNK  8
#define NKEY    1536                 // 3*w effective keys (z-sum collapses chunks)
#define NQROW   65536                // L * NH query rows of dim 64

// -------------------- scratch (no cudaMalloc allowed) --------------------
__device__ float g_qp  [NQROW * DHEAD];        // 16 MB (tf32-rounded)
__device__ float g_kvp [L_TOK * 2 * DHEAD];    // 2 MB
__device__ float g_keff[NKEY * DHEAD];         // tf32-rounded
__device__ float g_veff[NKEY * DHEAD];         // tf32-rounded
__device__ float g_ctx [NQROW * DHEAD];        // 16 MB (tf32-rounded)
__device__ float g_rq  [L_TOK * DMODEL];       // tf32-rounded inputs
__device__ float g_rkv [L_TOK * DMODEL];
__device__ float g_rWq [DMODEL * DMODEL];
__device__ float g_rWkv[DMODEL * 2 * DHEAD];
__device__ float g_rWc [DMODEL * DMODEL];

// -------------------- helpers --------------------
__device__ __forceinline__ float tf32r(float x) {
    unsigned u;
    asm("cvt.rna.tf32.f32 %0, %1;" : "=r"(u) : "f"(x));
    return __uint_as_float(u);
}

__device__ __forceinline__ void mma_tf32(float* c, const unsigned* a,
                                         unsigned b0, unsigned b1) {
    asm volatile(
        "mma.sync.aligned.m16n8k8.row.col.f32.tf32.tf32.f32 "
        "{%0,%1,%2,%3},{%4,%5,%6,%7},{%8,%9},{%0,%1,%2,%3};"
        : "+f"(c[0]), "+f"(c[1]), "+f"(c[2]), "+f"(c[3])
        : "r"(a[0]), "r"(a[1]), "r"(a[2]), "r"(a[3]), "r"(b0), "r"(b1));
}

__device__ __forceinline__ void cp_async16(void* smem_dst, const void* gmem_src) {
    unsigned s = (unsigned)__cvta_generic_to_shared(smem_dst);
    asm volatile("cp.async.ca.shared.global [%0], [%1], 16;\n"
                 :: "r"(s), "l"(gmem_src));
}
__device__ __forceinline__ void cp_commit() {
    asm volatile("cp.async.commit_group;\n" ::: "memory");
}

// -------------------- round inputs to tf32 (rna, unbiased) ----------------
__global__ void round_copy(const float* __restrict__ in, float* __restrict__ out, int n) {
    int i = (blockIdx.x * blockDim.x + threadIdx.x) * 4;
    if (i < n) {
        float4 v = *(const float4*)(in + i);
        v.x = tf32r(v.x); v.y = tf32r(v.y); v.z = tf32r(v.z); v.w = tf32r(v.w);
        *(float4*)(out + i) = v;
    }
}

// -------------------- TF32 tensor-core GEMM: C = alpha * A(MxK) B(KxN) ----
// 128x128 block tile, BK=32, 8 warps (4x2), warp tile 32x64.
// cp.async 2-stage double buffer. All inputs pre-rounded to tf32.
#define GEMM_AS_FLOATS (128 * 36)
#define GEMM_BS_FLOATS (32 * 132)
#define GEMM_SMEM_BYTES (2 * (GEMM_AS_FLOATS + GEMM_BS_FLOATS) * 4)

__global__ __launch_bounds__(256) void gemm_tf32(
    const float* __restrict__ A, const float* __restrict__ B,
    float* __restrict__ C, int M, int N, int K, float alpha, int round_out)
{
    extern __shared__ float sm[];
    float* AsBuf = sm;                               // 2 x [128][36]
    float* BsBuf = sm + 2 * GEMM_AS_FLOATS;          // 2 x [32][132]

    const int tid  = threadIdx.x;
    const int lane = tid & 31;
    const int warp = tid >> 5;
    const int wm = warp >> 1;        // 0..3
    const int wn = warp & 1;         // 0..1
    const int bm = blockIdx.y * 128;
    const int bn = blockIdx.x * 128;
    const int qr = lane >> 2;        // 0..7
    const int qc = lane & 3;         // 0..3

    auto issue = [&](int kt, int stage) {
        const float* Ag = A + (size_t)bm * K + kt * 32;
        const float* Bg = B + (size_t)(kt * 32) * N + bn;
        float* Asd = AsBuf + stage * GEMM_AS_FLOATS;
        float* Bsd = BsBuf + stage * GEMM_BS_FLOATS;
#pragma unroll
        for (int i = 0; i < 4; i++) {               // A: 128x32
            int idx = tid + i * 256;
            int r = idx >> 3, k4 = (idx & 7) * 4;
            cp_async16(Asd + r * 36 + k4, Ag + (size_t)r * K + k4);
        }
#pragma unroll
        for (int i = 0; i < 4; i++) {               // B: 32x128
            int idx = tid + i * 256;
            int kk = idx >> 5, n4 = (idx & 31) * 4;
            cp_async16(Bsd + kk * 132 + n4, Bg + (size_t)kk * N + n4);
        }
        cp_commit();
    };

    float acc[2][8][4];
#pragma unroll
    for (int mt = 0; mt < 2; mt++)
#pragma unroll
        for (int nt = 0; nt < 8; nt++)
#pragma unroll
            for (int i = 0; i < 4; i++) acc[mt][nt][i] = 0.f;

    const int NK = K / 32;
    issue(0, 0);
    for (int kt = 0; kt < NK; ++kt) {
        if (kt + 1 < NK) {
            issue(kt + 1, (kt + 1) & 1);
            asm volatile("cp.async.wait_group 1;\n" ::: "memory");
        } else {
            asm volatile("cp.async.wait_group 0;\n" ::: "memory");
        }
        __syncthreads();
        const float* Asd = AsBuf + (kt & 1) * GEMM_AS_FLOATS;
        const float* Bsd = BsBuf + (kt & 1) * GEMM_BS_FLOATS;

#pragma unroll
        for (int kk = 0; kk < 4; ++kk) {
            const int k0 = kk * 8;
            unsigned a[2][4];
#pragma unroll
            for (int mt = 0; mt < 2; ++mt) {
                int r = wm * 32 + mt * 16 + qr;
                a[mt][0] = __float_as_uint(Asd[r * 36 + k0 + qc]);
                a[mt][1] = __float_as_uint(Asd[(r + 8) * 36 + k0 + qc]);
                a[mt][2] = __float_as_uint(Asd[r * 36 + k0 + 4 + qc]);
                a[mt][3] = __float_as_uint(Asd[(r + 8) * 36 + k0 + 4 + qc]);
            }
#pragma unroll
            for (int nt = 0; nt < 8; ++nt) {
                int c = wn * 64 + nt * 8 + qr;
                unsigned b0 = __float_as_uint(Bsd[(k0 + qc) * 132 + c]);
                unsigned b1 = __float_as_uint(Bsd[(k0 + 4 + qc) * 132 + c]);
                mma_tf32(acc[0][nt], a[0], b0, b1);
                mma_tf32(acc[1][nt], a[1], b0, b1);
            }
        }
        __syncthreads();
    }

#pragma unroll
    for (int mt = 0; mt < 2; ++mt) {
#pragma unroll
        for (int nt = 0; nt < 8; ++nt) {
            int r = bm + wm * 32 + mt * 16 + qr;
            int c = bn + wn * 64 + nt * 8 + qc * 2;
            float v0 = alpha * acc[mt][nt][0];
            float v1 = alpha * acc[mt][nt][1];
            float v2 = alpha * acc[mt][nt][2];
            float v3 = alpha * acc[mt][nt][3];
            if (round_out) { v0 = tf32r(v0); v1 = tf32r(v1); v2 = tf32r(v2); v3 = tf32r(v3); }
            float2 p0 = make_float2(v0, v1);
            float2 p1 = make_float2(v2, v3);
            *(float2*)&C[(size_t)r * N + c] = p0;
            *(float2*)&C[(size_t)(r + 8) * N + c] = p1;
        }
    }
}

// -------------------- build K_eff / V_eff (tf32-rounded outputs) ----------
__global__ void build_eff(const float* __restrict__ kvp,
                          float* __restrict__ keff, float* __restrict__ veff)
{
    int idx = blockIdx.x * blockDim.x + threadIdx.x;
    if (idx >= WCHUNK * DHEAD) return;
    int y = idx >> 6;
    int d = idx & 63;

    float ks = 0.f, vs = 0.f, kf = 0.f, vf = 0.f, kl = 0.f, vl = 0.f;
#pragma unroll
    for (int c = 0; c < NCHUNK; c++) {
        const float* row = kvp + (size_t)((c << 9) + y) * (2 * DHEAD);
        float kx = row[d];
        float vx = row[DHEAD + d];
        if (c == 0)          { kf = kx; vf = vx; }
        if (c == NCHUNK - 1) { kl = kx; vl = vx; }
        ks += kx; vs += vx;
    }
    keff[(0 * WCHUNK + y) * DHEAD + d] = tf32r(ks - kl);
    keff[(1 * WCHUNK + y) * DHEAD + d] = tf32r(ks);
    keff[(2 * WCHUNK + y) * DHEAD + d] = tf32r(ks - kf);
    veff[(0 * WCHUNK + y) * DHEAD + d] = tf32r(vs - vl);
    veff[(1 * WCHUNK + y) * DHEAD + d] = tf32r(vs);
    veff[(2 * WCHUNK + y) * DHEAD + d] = tf32r(vs - vf);
}

// -------------------- TF32 flash attention --------------------------------
// 128 query rows / block (8 warps x 16 rows), K/V tiles of 64 keys,
// cp.async double-buffered. Q fragments live in registers for all 24 tiles.
// P never hits smem: S C-fragments are shuffled into PV A-fragments.
#define KT 64
#define KV_STAGE_FLOATS (2 * KT * 68)          // Ks + Vs per stage
#define ATTN_SMEM_BYTES (2 * KV_STAGE_FLOATS * 4)
#define NKT (NKEY / KT)                        // 24

__global__ __launch_bounds__(256) void attn_tf32(
    const float* __restrict__ Q, const float* __restrict__ Ke,
    const float* __restrict__ Ve, float* __restrict__ O)
{
    extern __shared__ float sm[];
    const int tid  = threadIdx.x;
    const int lane = tid & 31;
    const int warp = tid >> 5;
    const int qr = lane >> 2;        // 0..7
    const int qc = lane & 3;         // 0..3
    const int qbase = blockIdx.x * 128;
    const int row0 = warp * 16 + qr; // local row of c0/c1; row0+8 for c2/c3

    auto issueKV = [&](int kt, int stage) {
        const float* Kg = Ke + (size_t)(kt * KT) * DHEAD;
        const float* Vg = Ve + (size_t)(kt * KT) * DHEAD;
        float* Kd = sm + stage * KV_STAGE_FLOATS;
        float* Vd = Kd + KT * 68;
#pragma unroll
        for (int i = 0; i < 4; i++) {           // 64 rows x 16 float4
            int idx = tid + i * 256;
            int r = idx >> 4, c4 = (idx & 15) * 4;
            cp_async16(Kd + r * 68 + c4, Kg + (size_t)r * DHEAD + c4);
            cp_async16(Vd + r * 68 + c4, Vg + (size_t)r * DHEAD + c4);
        }
        cp_commit();
    };

    // Q fragments: 8 k-steps over dh=64 (Q pre-rounded to tf32 by gemm epilogue)
    unsigned aq[8][4];
    {
        const float* q0 = Q + (size_t)(qbase + row0) * DHEAD;
        const float* q8 = q0 + 8 * DHEAD;
#pragma unroll
        for (int kk = 0; kk < 8; kk++) {
            int c = kk * 8 + qc;
            aq[kk][0] = __float_as_uint(q0[c]);
            aq[kk][1] = __float_as_uint(q8[c]);
            aq[kk][2] = __float_as_uint(q0[c + 4]);
            aq[kk][3] = __float_as_uint(q8[c + 4]);
        }
    }

    float oacc[8][4];
#pragma unroll
    for (int n = 0; n < 8; n++)
#pragma unroll
        for (int i = 0; i < 4; i++) oacc[n][i] = 0.f;
    float m0 = -1e30f, m1 = -1e30f, l0 = 0.f, l1 = 0.f;

    issueKV(0, 0);
    for (int kt = 0; kt < NKT; ++kt) {
        if (kt + 1 < NKT) {
            issueKV(kt + 1, (kt + 1) & 1);
            asm volatile("cp.async.wait_group 1;\n" ::: "memory");
        } else {
            asm volatile("cp.async.wait_group 0;\n" ::: "memory");
        }
        __syncthreads();
        const float* Ks = sm + (kt & 1) * KV_STAGE_FLOATS;
        const float* Vs = Ks + KT * 68;

        // ---- S = Q K^T (16 rows x 64 keys per warp) ----
        float p[8][4];
#pragma unroll
        for (int nt = 0; nt < 8; nt++)
#pragma unroll
            for (int i = 0; i < 4; i++) p[nt][i] = 0.f;

#pragma unroll
        for (int kk = 0; kk < 8; ++kk) {
            const int k0 = kk * 8;
#pragma unroll
            for (int nt = 0; nt < 8; ++nt) {
                int keyr = nt * 8 + qr;
                unsigned b0 = __float_as_uint(Ks[keyr * 68 + k0 + qc]);
                unsigned b1 = __float_as_uint(Ks[keyr * 68 + k0 + 4 + qc]);
                mma_tf32(p[nt], aq[kk], b0, b1);
            }
        }

        // ---- online softmax (rows warp-local; quad lanes share a row) ----
        float rm0 = -1e30f, rm1 = -1e30f;
#pragma unroll
        for (int nt = 0; nt < 8; nt++) {
            rm0 = fmaxf(rm0, fmaxf(p[nt][0], p[nt][1]));
            rm1 = fmaxf(rm1, fmaxf(p[nt][2], p[nt][3]));
        }
        rm0 = fmaxf(rm0, __shfl_xor_sync(0xffffffffu, rm0, 1));
        rm0 = fmaxf(rm0, __shfl_xor_sync(0xffffffffu, rm0, 2));
        rm1 = fmaxf(rm1, __shfl_xor_sync(0xffffffffu, rm1, 1));
        rm1 = fmaxf(rm1, __shfl_xor_sync(0xffffffffu, rm1, 2));
        float mn0 = fmaxf(m0, rm0), mn1 = fmaxf(m1, rm1);
        float c0 = __expf(m0 - mn0), c1 = __expf(m1 - mn1);
        m0 = mn0; m1 = mn1;

        float rs0 = 0.f, rs1 = 0.f;
#pragma unroll
        for (int nt = 0; nt < 8; nt++) {
            p[nt][0] = __expf(p[nt][0] - mn0);
            p[nt][1] = __expf(p[nt][1] - mn0);
            p[nt][2] = __expf(p[nt][2] - mn1);
            p[nt][3] = __expf(p[nt][3] - mn1);
            rs0 += p[nt][0] + p[nt][1];
            rs1 += p[nt][2] + p[nt][3];
        }
        rs0 += __shfl_xor_sync(0xffffffffu, rs0, 1);
        rs0 += __shfl_xor_sync(0xffffffffu, rs0, 2);
        rs1 += __shfl_xor_sync(0xffffffffu, rs1, 1);
        rs1 += __shfl_xor_sync(0xffffffffu, rs1, 2);
        l0 = l0 * c0 + rs0;
        l1 = l1 * c1 + rs1;
#pragma unroll
        for (int n = 0; n < 8; n++) {
            oacc[n][0] *= c0; oacc[n][1] *= c0;
            oacc[n][2] *= c1; oacc[n][3] *= c1;
        }

        // ---- O += P V : shuffle C-frag(p) -> A-frag, then mma over Vs ----
        const int base = lane & ~3;
        const int s0 = base + (qc >> 1);
        const int s1 = s0 + 2;
        const bool odd = (qc & 1);
#pragma unroll
        for (int j = 0; j < 8; ++j) {       // PV k-tiles == S n-tiles
            float x0 = __shfl_sync(0xffffffffu, p[j][0], s0);
            float x1 = __shfl_sync(0xffffffffu, p[j][1], s0);
            float x2 = __shfl_sync(0xffffffffu, p[j][2], s0);
            float x3 = __shfl_sync(0xffffffffu, p[j][3], s0);
            float y0 = __shfl_sync(0xffffffffu, p[j][0], s1);
            float y1 = __shfl_sync(0xffffffffu, p[j][1], s1);
            float y2 = __shfl_sync(0xffffffffu, p[j][2], s1);
            float y3 = __shfl_sync(0xffffffffu, p[j][3], s1);
            unsigned pa[4];
            pa[0] = __float_as_uint(tf32r(odd ? x1 : x0));   // (r,   c)
            pa[1] = __float_as_uint(tf32r(odd ? x3 : x2));   // (r+8, c)
            pa[2] = __float_as_uint(tf32r(odd ? y1 : y0));   // (r,   c+4)
            pa[3] = __float_as_uint(tf32r(odd ? y3 : y2));   // (r+8, c+4)
            const int kr = j * 8 + qc;
#pragma unroll
            for (int n = 0; n < 8; ++n) {
                unsigned b0 = __float_as_uint(Vs[kr * 68 + n * 8 + qr]);
                unsigned b1 = __float_as_uint(Vs[(kr + 4) * 68 + n * 8 + qr]);
                mma_tf32(oacc[n], pa, b0, b1);
            }
        }
        __syncthreads();
    }

    // ---- finalize: O / l, rounded to tf32 (feeds the Wc GEMM) ----
    float inv0 = 1.f / l0, inv1 = 1.f / l1;
#pragma unroll
    for (int n = 0; n < 8; ++n) {
        int c = n * 8 + qc * 2;
        float2 v0 = make_float2(tf32r(oacc[n][0] * inv0), tf32r(oacc[n][1] * inv0));
        float2 v1 = make_float2(tf32r(oacc[n][2] * inv1), tf32r(oacc[n][3] * inv1));
        *(float2*)&O[(size_t)(qbase + row0) * DHEAD + c] = v0;
        *(float2*)&O[(size_t)(qbase + row0 + 8) * DHEAD + c] = v1;
    }
}

// -------------------- launch --------------------
extern "C" void kernel_launch(void* const* d_in, const int* in_sizes, int n_in,
                              void* d_out, int out_size)
{
    const float* q   = (const float*)d_in[0];
    const float* kv  = (const float*)d_in[1];
    const float* Wq  = (const float*)d_in[2];
    const float* Wkv = (const float*)d_in[3];
    const float* Wc  = (const float*)d_in[4];
    float* out = (float*)d_out;

    float *qp, *kvp, *keff, *veff, *ctx, *rq, *rkv, *rWq, *rWkv, *rWc;
    cudaGetSymbolAddress((void**)&qp,   g_qp);
    cudaGetSymbolAddress((void**)&kvp,  g_kvp);
    cudaGetSymbolAddress((void**)&keff, g_keff);
    cudaGetSymbolAddress((void**)&veff, g_veff);
    cudaGetSymbolAddress((void**)&ctx,  g_ctx);
    cudaGetSymbolAddress((void**)&rq,   g_rq);
    cudaGetSymbolAddress((void**)&rkv,  g_rkv);
    cudaGetSymbolAddress((void**)&rWq,  g_rWq);
    cudaGetSymbolAddress((void**)&rWkv, g_rWkv);
    cudaGetSymbolAddress((void**)&rWc,  g_rWc);

    cudaFuncSetAttribute(gemm_tf32,
                         cudaFuncAttributeMaxDynamicSharedMemorySize,
                         GEMM_SMEM_BYTES);
    cudaFuncSetAttribute(attn_tf32,
                         cudaFuncAttributeMaxDynamicSharedMemorySize,
                         ATTN_SMEM_BYTES);

    // unbiased tf32 rounding of all mma inputs
    round_copy<<<4096, 256>>>(q,   rq,   L_TOK * DMODEL);
    round_copy<<<4096, 256>>>(kv,  rkv,  L_TOK * DMODEL);
    round_copy<<<1024, 256>>>(Wq,  rWq,  DMODEL * DMODEL);
    round_copy<<< 128, 256>>>(Wkv, rWkv, DMODEL * 2 * DHEAD);
    round_copy<<<1024, 256>>>(Wc,  rWc,  DMODEL * DMODEL);

    // kvp = kv @ Wkv  (4096 x 128 x 1024)
    gemm_tf32<<<dim3(1, 32), 256, GEMM_SMEM_BYTES>>>(
        rkv, rWkv, kvp, L_TOK, 2 * DHEAD, DMODEL, 1.0f, 0);
    // K_eff / V_eff chunk sums (tf32-rounded)
    build_eff<<<(WCHUNK * DHEAD + 255) / 256, 256>>>(kvp, keff, veff);
    // qp = (q @ Wq) / 8  (4096 x 1024 x 1024), rounded for attention
    gemm_tf32<<<dim3(8, 32), 256, GEMM_SMEM_BYTES>>>(
        rq, rWq, qp, L_TOK, DMODEL, DMODEL, 0.125f, 1);
    // attention: Q[65536,64] vs shared K/V[1536,64]
    attn_tf32<<<NQROW / 128, 256, ATTN_SMEM_BYTES>>>(qp, keff, veff, ctx);
    // out = ctx @ Wc  (4096 x 1024 x 1024), plain fp32 output
    gemm_tf32<<<dim3(8, 32), 256, GEMM_SMEM_BYTES>>>(
        ctx, rWc, out, L_TOK, DMODEL, DMODEL, 1.0f, 0);
}

// round 7
// speedup vs baseline: 5.4186x; 1.4719x over previous
#include <cuda_runtime.h>
#include <cuda_bf16.h>
#include <math.h>

// Problem constants (B=1, L=4096, DM=1024, NH=16, DH=64, w=512, C=8)
#define L_TOK   4096
#define DMODEL  1024
#define DHEAD   64
#define WCHUNK  512
#define NCHUNK  8
#define NKEY    1536                 // 3*w effective keys (z-sum collapses chunks)
#define NQROW   65536                // L * NH query rows of dim 64

// -------------------- scratch (no cudaMalloc allowed) --------------------
__device__ float g_qp  [NQROW * DHEAD];        // 16 MB (tf32-rounded)
__device__ float g_kvp [L_TOK * 2 * DHEAD];    // 2 MB
__device__ float g_keff[NKEY * DHEAD];         // tf32-rounded
__device__ float g_veff[NKEY * DHEAD];         // tf32-rounded
__device__ float g_ctx [NQROW * DHEAD];        // 16 MB (tf32-rounded)

// -------------------- helpers --------------------
__device__ __forceinline__ float tf32r(float x) {
    unsigned u;
    asm("cvt.rna.tf32.f32 %0, %1;" : "=r"(u) : "f"(x));
    return __uint_as_float(u);
}

__device__ __forceinline__ void mma_tf32(float* c, const unsigned* a,
                                         unsigned b0, unsigned b1) {
    asm volatile(
        "mma.sync.aligned.m16n8k8.row.col.f32.tf32.tf32.f32 "
        "{%0,%1,%2,%3},{%4,%5,%6,%7},{%8,%9},{%0,%1,%2,%3};"
        : "+f"(c[0]), "+f"(c[1]), "+f"(c[2]), "+f"(c[3])
        : "r"(a[0]), "r"(a[1]), "r"(a[2]), "r"(a[3]), "r"(b0), "r"(b1));
}

__device__ __forceinline__ void cp_async16(void* smem_dst, const void* gmem_src) {
    unsigned s = (unsigned)__cvta_generic_to_shared(smem_dst);
    asm volatile("cp.async.ca.shared.global [%0], [%1], 16;\n"
                 :: "r"(s), "l"(gmem_src));
}
__device__ __forceinline__ void cp_commit() {
    asm volatile("cp.async.commit_group;\n" ::: "memory");
}

// -------------------- TF32 tensor-core GEMM: C = alpha * A(MxK) B(KxN) ----
// 128x128 block tile, BK=32, 8 warps (4x2), warp tile 32x64.
// cp.async 2-stage double buffer. RA/RB: round operand to tf32 (rna) at
// fragment load (fuses the old round_copy pass into the GEMM).
#define GEMM_AS_FLOATS (128 * 36)
#define GEMM_BS_FLOATS (32 * 132)
#define GEMM_SMEM_BYTES (2 * (GEMM_AS_FLOATS + GEMM_BS_FLOATS) * 4)

template<int RA, int RB>
__global__ __launch_bounds__(256) void gemm_tf32(
    const float* __restrict__ A, const float* __restrict__ B,
    float* __restrict__ C, int M, int N, int K, float alpha, int round_out)
{
    extern __shared__ float sm[];
    float* AsBuf = sm;                               // 2 x [128][36]
    float* BsBuf = sm + 2 * GEMM_AS_FLOATS;          // 2 x [32][132]

    const int tid  = threadIdx.x;
    const int lane = tid & 31;
    const int warp = tid >> 5;
    const int wm = warp >> 1;        // 0..3
    const int wn = warp & 1;         // 0..1
    const int bm = blockIdx.y * 128;
    const int bn = blockIdx.x * 128;
    const int qr = lane >> 2;        // 0..7
    const int qc = lane & 3;         // 0..3

    auto issue = [&](int kt, int stage) {
        const float* Ag = A + (size_t)bm * K + kt * 32;
        const float* Bg = B + (size_t)(kt * 32) * N + bn;
        float* Asd = AsBuf + stage * GEMM_AS_FLOATS;
        float* Bsd = BsBuf + stage * GEMM_BS_FLOATS;
#pragma unroll
        for (int i = 0; i < 4; i++) {               // A: 128x32
            int idx = tid + i * 256;
            int r = idx >> 3, k4 = (idx & 7) * 4;
            cp_async16(Asd + r * 36 + k4, Ag + (size_t)r * K + k4);
        }
#pragma unroll
        for (int i = 0; i < 4; i++) {               // B: 32x128
            int idx = tid + i * 256;
            int kk = idx >> 5, n4 = (idx & 31) * 4;
            cp_async16(Bsd + kk * 132 + n4, Bg + (size_t)kk * N + n4);
        }
        cp_commit();
    };

    float acc[2][8][4];
#pragma unroll
    for (int mt = 0; mt < 2; mt++)
#pragma unroll
        for (int nt = 0; nt < 8; nt++)
#pragma unroll
            for (int i = 0; i < 4; i++) acc[mt][nt][i] = 0.f;

    const int NK = K / 32;
    issue(0, 0);
    for (int kt = 0; kt < NK; ++kt) {
        if (kt + 1 < NK) {
            issue(kt + 1, (kt + 1) & 1);
            asm volatile("cp.async.wait_group 1;\n" ::: "memory");
        } else {
            asm volatile("cp.async.wait_group 0;\n" ::: "memory");
        }
        __syncthreads();
        const float* Asd = AsBuf + (kt & 1) * GEMM_AS_FLOATS;
        const float* Bsd = BsBuf + (kt & 1) * GEMM_BS_FLOATS;

#pragma unroll
        for (int kk = 0; kk < 4; ++kk) {
            const int k0 = kk * 8;
            unsigned a[2][4];
#pragma unroll
            for (int mt = 0; mt < 2; ++mt) {
                int r = wm * 32 + mt * 16 + qr;
                float a0 = Asd[r * 36 + k0 + qc];
                float a1 = Asd[(r + 8) * 36 + k0 + qc];
                float a2 = Asd[r * 36 + k0 + 4 + qc];
                float a3 = Asd[(r + 8) * 36 + k0 + 4 + qc];
                if (RA) { a0 = tf32r(a0); a1 = tf32r(a1); a2 = tf32r(a2); a3 = tf32r(a3); }
                a[mt][0] = __float_as_uint(a0);
                a[mt][1] = __float_as_uint(a1);
                a[mt][2] = __float_as_uint(a2);
                a[mt][3] = __float_as_uint(a3);
            }
#pragma unroll
            for (int nt = 0; nt < 8; ++nt) {
                int c = wn * 64 + nt * 8 + qr;
                float bf0 = Bsd[(k0 + qc) * 132 + c];
                float bf1 = Bsd[(k0 + 4 + qc) * 132 + c];
                if (RB) { bf0 = tf32r(bf0); bf1 = tf32r(bf1); }
                unsigned b0 = __float_as_uint(bf0);
                unsigned b1 = __float_as_uint(bf1);
                mma_tf32(acc[0][nt], a[0], b0, b1);
                mma_tf32(acc[1][nt], a[1], b0, b1);
            }
        }
        __syncthreads();
    }

#pragma unroll
    for (int mt = 0; mt < 2; ++mt) {
#pragma unroll
        for (int nt = 0; nt < 8; ++nt) {
            int r = bm + wm * 32 + mt * 16 + qr;
            int c = bn + wn * 64 + nt * 8 + qc * 2;
            float v0 = alpha * acc[mt][nt][0];
            float v1 = alpha * acc[mt][nt][1];
            float v2 = alpha * acc[mt][nt][2];
            float v3 = alpha * acc[mt][nt][3];
            if (round_out) { v0 = tf32r(v0); v1 = tf32r(v1); v2 = tf32r(v2); v3 = tf32r(v3); }
            *(float2*)&C[(size_t)r * N + c] = make_float2(v0, v1);
            *(float2*)&C[(size_t)(r + 8) * N + c] = make_float2(v2, v3);
        }
    }
}

// -------------------- build K_eff / V_eff (tf32-rounded outputs) ----------
__global__ void build_eff(const float* __restrict__ kvp,
                          float* __restrict__ keff, float* __restrict__ veff)
{
    int idx = blockIdx.x * blockDim.x + threadIdx.x;
    if (idx >= WCHUNK * DHEAD) return;
    int y = idx >> 6;
    int d = idx & 63;

    float ks = 0.f, vs = 0.f, kf = 0.f, vf = 0.f, kl = 0.f, vl = 0.f;
#pragma unroll
    for (int c = 0; c < NCHUNK; c++) {
        const float* row = kvp + (size_t)((c << 9) + y) * (2 * DHEAD);
        float kx = row[d];
        float vx = row[DHEAD + d];
        if (c == 0)          { kf = kx; vf = vx; }
        if (c == NCHUNK - 1) { kl = kx; vl = vx; }
        ks += kx; vs += vx;
    }
    keff[(0 * WCHUNK + y) * DHEAD + d] = tf32r(ks - kl);
    keff[(1 * WCHUNK + y) * DHEAD + d] = tf32r(ks);
    keff[(2 * WCHUNK + y) * DHEAD + d] = tf32r(ks - kf);
    veff[(0 * WCHUNK + y) * DHEAD + d] = tf32r(vs - vl);
    veff[(1 * WCHUNK + y) * DHEAD + d] = tf32r(vs);
    veff[(2 * WCHUNK + y) * DHEAD + d] = tf32r(vs - vf);
}

// -------------------- TF32 flash attention --------------------------------
// 256 query rows / block (8 warps x 32 rows = 2 m-tiles/warp).
// K/V tiles of 64 keys, cp.async double-buffered.
// No online max: scores are provably small (|S| < ~10), exp(S) is safe;
// normalization by l at the end is mathematically identical to softmax.
// B-fragments (K and V) are loaded from smem ONCE and shared across both
// m-tiles, halving LDS traffic per FLOP.
#define KT 64
#define KV_STAGE_FLOATS (2 * KT * 68)          // Ks + Vs per stage
#define ATTN_SMEM_BYTES (2 * KV_STAGE_FLOATS * 4)
#define NKT (NKEY / KT)                        // 24

__global__ __launch_bounds__(256) void attn_tf32(
    const float* __restrict__ Q, const float* __restrict__ Ke,
    const float* __restrict__ Ve, float* __restrict__ O)
{
    extern __shared__ float sm[];
    const int tid  = threadIdx.x;
    const int lane = tid & 31;
    const int warp = tid >> 5;
    const int qr = lane >> 2;        // 0..7
    const int qc = lane & 3;         // 0..3
    const int qbase = blockIdx.x * 256;
    const int row0 = warp * 32 + qr; // +mt*16 per m-tile; +8 for c2/c3

    auto issueKV = [&](int kt, int stage) {
        const float* Kg = Ke + (size_t)(kt * KT) * DHEAD;
        const float* Vg = Ve + (size_t)(kt * KT) * DHEAD;
        float* Kd = sm + stage * KV_STAGE_FLOATS;
        float* Vd = Kd + KT * 68;
#pragma unroll
        for (int i = 0; i < 4; i++) {           // 64 rows x 16 float4
            int idx = tid + i * 256;
            int r = idx >> 4, c4 = (idx & 15) * 4;
            cp_async16(Kd + r * 68 + c4, Kg + (size_t)r * DHEAD + c4);
            cp_async16(Vd + r * 68 + c4, Vg + (size_t)r * DHEAD + c4);
        }
        cp_commit();
    };

    // Q fragments for both m-tiles (Q pre-rounded to tf32 by gemm epilogue)
    unsigned aq[2][8][4];
#pragma unroll
    for (int mt = 0; mt < 2; mt++) {
        const float* q0 = Q + (size_t)(qbase + row0 + mt * 16) * DHEAD;
        const float* q8 = q0 + 8 * DHEAD;
#pragma unroll
        for (int kk = 0; kk < 8; kk++) {
            int c = kk * 8 + qc;
            aq[mt][kk][0] = __float_as_uint(q0[c]);
            aq[mt][kk][1] = __float_as_uint(q8[c]);
            aq[mt][kk][2] = __float_as_uint(q0[c + 4]);
            aq[mt][kk][3] = __float_as_uint(q8[c + 4]);
        }
    }

    float oacc[2][8][4];
#pragma unroll
    for (int mt = 0; mt < 2; mt++)
#pragma unroll
        for (int n = 0; n < 8; n++)
#pragma unroll
            for (int i = 0; i < 4; i++) oacc[mt][n][i] = 0.f;
    float lp0[2] = {0.f, 0.f};   // per-lane partial row sums (rows r / r+8)
    float lp1[2] = {0.f, 0.f};

    const int base = lane & ~3;
    const int s0 = base + (qc >> 1);
    const int s1 = s0 + 2;
    const bool odd = (qc & 1);

    issueKV(0, 0);
    for (int kt = 0; kt < NKT; ++kt) {
        if (kt + 1 < NKT) {
            issueKV(kt + 1, (kt + 1) & 1);
            asm volatile("cp.async.wait_group 1;\n" ::: "memory");
        } else {
            asm volatile("cp.async.wait_group 0;\n" ::: "memory");
        }
        __syncthreads();
        const float* Ks = sm + (kt & 1) * KV_STAGE_FLOATS;
        const float* Vs = Ks + KT * 68;

        // ---- S = Q K^T for both m-tiles, B-frags loaded once ----
        float p[2][8][4];
#pragma unroll
        for (int mt = 0; mt < 2; mt++)
#pragma unroll
            for (int nt = 0; nt < 8; nt++)
#pragma unroll
                for (int i = 0; i < 4; i++) p[mt][nt][i] = 0.f;

#pragma unroll
        for (int kk = 0; kk < 8; ++kk) {
            const int k0 = kk * 8;
#pragma unroll
            for (int nt = 0; nt < 8; ++nt) {
                int keyr = nt * 8 + qr;
                unsigned b0 = __float_as_uint(Ks[keyr * 68 + k0 + qc]);
                unsigned b1 = __float_as_uint(Ks[keyr * 68 + k0 + 4 + qc]);
                mma_tf32(p[0][nt], aq[0][kk], b0, b1);
                mma_tf32(p[1][nt], aq[1][kk], b0, b1);
            }
        }

        // ---- exp (no max subtraction: scores bounded ~|10|) + l partials --
#pragma unroll
        for (int mt = 0; mt < 2; mt++)
#pragma unroll
            for (int nt = 0; nt < 8; nt++) {
                p[mt][nt][0] = __expf(p[mt][nt][0]);
                p[mt][nt][1] = __expf(p[mt][nt][1]);
                p[mt][nt][2] = __expf(p[mt][nt][2]);
                p[mt][nt][3] = __expf(p[mt][nt][3]);
                lp0[mt] += p[mt][nt][0] + p[mt][nt][1];
                lp1[mt] += p[mt][nt][2] + p[mt][nt][3];
            }

        // ---- O += P V : shuffle C-frag -> A-frag; V B-frags shared ------
#pragma unroll
        for (int j = 0; j < 8; ++j) {        // PV k-tiles == S n-tiles
            unsigned pa[2][4];
#pragma unroll
            for (int mt = 0; mt < 2; mt++) {
                float x0 = __shfl_sync(0xffffffffu, p[mt][j][0], s0);
                float x1 = __shfl_sync(0xffffffffu, p[mt][j][1], s0);
                float x2 = __shfl_sync(0xffffffffu, p[mt][j][2], s0);
                float x3 = __shfl_sync(0xffffffffu, p[mt][j][3], s0);
                float y0 = __shfl_sync(0xffffffffu, p[mt][j][0], s1);
                float y1 = __shfl_sync(0xffffffffu, p[mt][j][1], s1);
                float y2 = __shfl_sync(0xffffffffu, p[mt][j][2], s1);
                float y3 = __shfl_sync(0xffffffffu, p[mt][j][3], s1);
                pa[mt][0] = __float_as_uint(tf32r(odd ? x1 : x0)); // (r,   c)
                pa[mt][1] = __float_as_uint(tf32r(odd ? x3 : x2)); // (r+8, c)
                pa[mt][2] = __float_as_uint(tf32r(odd ? y1 : y0)); // (r,   c+4)
                pa[mt][3] = __float_as_uint(tf32r(odd ? y3 : y2)); // (r+8, c+4)
            }
            const int kr = j * 8 + qc;
#pragma unroll
            for (int n = 0; n < 8; ++n) {
                unsigned b0 = __float_as_uint(Vs[kr * 68 + n * 8 + qr]);
                unsigned b1 = __float_as_uint(Vs[(kr + 4) * 68 + n * 8 + qr]);
                mma_tf32(oacc[0][n], pa[0], b0, b1);
                mma_tf32(oacc[1][n], pa[1], b0, b1);
            }
        }
        __syncthreads();
    }

    // ---- finalize: reduce l across quad lanes, O / l, round to tf32 -----
#pragma unroll
    for (int mt = 0; mt < 2; mt++) {
        float l0 = lp0[mt], l1 = lp1[mt];
        l0 += __shfl_xor_sync(0xffffffffu, l0, 1);
        l0 += __shfl_xor_sync(0xffffffffu, l0, 2);
        l1 += __shfl_xor_sync(0xffffffffu, l1, 1);
        l1 += __shfl_xor_sync(0xffffffffu, l1, 2);
        float inv0 = 1.f / l0, inv1 = 1.f / l1;
        const int r = qbase + row0 + mt * 16;
#pragma unroll
        for (int n = 0; n < 8; ++n) {
            int c = n * 8 + qc * 2;
            float2 v0 = make_float2(tf32r(oacc[mt][n][0] * inv0),
                                    tf32r(oacc[mt][n][1] * inv0));
            float2 v1 = make_float2(tf32r(oacc[mt][n][2] * inv1),
                                    tf32r(oacc[mt][n][3] * inv1));
            *(float2*)&O[(size_t)r * DHEAD + c] = v0;
            *(float2*)&O[(size_t)(r + 8) * DHEAD + c] = v1;
        }
    }
}

// -------------------- launch --------------------
extern "C" void kernel_launch(void* const* d_in, const int* in_sizes, int n_in,
                              void* d_out, int out_size)
{
    const float* q   = (const float*)d_in[0];
    const float* kv  = (const float*)d_in[1];
    const float* Wq  = (const float*)d_in[2];
    const float* Wkv = (const float*)d_in[3];
    const float* Wc  = (const float*)d_in[4];
    float* out = (float*)d_out;

    float *qp, *kvp, *keff, *veff, *ctx;
    cudaGetSymbolAddress((void**)&qp,   g_qp);
    cudaGetSymbolAddress((void**)&kvp,  g_kvp);
    cudaGetSymbolAddress((void**)&keff, g_keff);
    cudaGetSymbolAddress((void**)&veff, g_veff);
    cudaGetSymbolAddress((void**)&ctx,  g_ctx);

    cudaFuncSetAttribute(gemm_tf32<1,1>,
                         cudaFuncAttributeMaxDynamicSharedMemorySize,
                         GEMM_SMEM_BYTES);
    cudaFuncSetAttribute(gemm_tf32<0,1>,
                         cudaFuncAttributeMaxDynamicSharedMemorySize,
                         GEMM_SMEM_BYTES);
    cudaFuncSetAttribute(attn_tf32,
                         cudaFuncAttributeMaxDynamicSharedMemorySize,
                         ATTN_SMEM_BYTES);

    // kvp = kv @ Wkv  (4096 x 128 x 1024), inputs rounded at frag load
    gemm_tf32<1,1><<<dim3(1, 32), 256, GEMM_SMEM_BYTES>>>(
        kv, Wkv, kvp, L_TOK, 2 * DHEAD, DMODEL, 1.0f, 0);
    // K_eff / V_eff chunk sums (tf32-rounded)
    build_eff<<<(WCHUNK * DHEAD + 255) / 256, 256>>>(kvp, keff, veff);
    // qp = (q @ Wq) / 8  (4096 x 1024 x 1024), rounded output for attention
    gemm_tf32<1,1><<<dim3(8, 32), 256, GEMM_SMEM_BYTES>>>(
        q, Wq, qp, L_TOK, DMODEL, DMODEL, 0.125f, 1);
    // attention: Q[65536,64] vs shared K/V[1536,64], 256 rows/block
    attn_tf32<<<NQROW / 256, 256, ATTN_SMEM_BYTES>>>(qp, keff, veff, ctx);
    // out = ctx @ Wc  (ctx already tf32; round only Wc at frag load)
    gemm_tf32<0,1><<<dim3(8, 32), 256, GEMM_SMEM_BYTES>>>(
        ctx, Wc, out, L_TOK, DMODEL, DMODEL, 1.0f, 0);
}

// round 8
// speedup vs baseline: 6.1812x; 1.1407x over previous
#include <cuda_runtime.h>
#include <cuda_bf16.h>
#include <math.h>

// Problem constants (B=1, L=4096, DM=1024, NH=16, DH=64, w=512, C=8)
#define L_TOK   4096
#define DMODEL  1024
#define DHEAD   64
#define WCHUNK  512
#define NCHUNK  8
#define NKEY    1536                 // 3*w effective keys (z-sum collapses chunks)
#define NQROW   65536                // L * NH query rows of dim 64
#define NSPLIT  4                    // split-K factor for the kvp GEMM

// -------------------- scratch (no cudaMalloc allowed) --------------------
__device__ float g_qp  [NQROW * DHEAD];               // 16 MB (tf32-rounded)
__device__ float g_kvp [NSPLIT * L_TOK * 2 * DHEAD];  // 8 MB (split-K partials)
__device__ float g_keff[NKEY * DHEAD];                // tf32-rounded
__device__ float g_veff[NKEY * DHEAD];                // tf32-rounded
__device__ float g_ctx [NQROW * DHEAD];               // 16 MB (tf32-rounded)

// -------------------- helpers --------------------
__device__ __forceinline__ float tf32r(float x) {
    unsigned u;
    asm("cvt.rna.tf32.f32 %0, %1;" : "=r"(u) : "f"(x));
    return __uint_as_float(u);
}

__device__ __forceinline__ void mma_tf32(float* c, const unsigned* a,
                                         unsigned b0, unsigned b1) {
    asm volatile(
        "mma.sync.aligned.m16n8k8.row.col.f32.tf32.tf32.f32 "
        "{%0,%1,%2,%3},{%4,%5,%6,%7},{%8,%9},{%0,%1,%2,%3};"
        : "+f"(c[0]), "+f"(c[1]), "+f"(c[2]), "+f"(c[3])
        : "r"(a[0]), "r"(a[1]), "r"(a[2]), "r"(a[3]), "r"(b0), "r"(b1));
}

__device__ __forceinline__ void cp_async16(void* smem_dst, const void* gmem_src) {
    unsigned s = (unsigned)__cvta_generic_to_shared(smem_dst);
    asm volatile("cp.async.ca.shared.global [%0], [%1], 16;\n"
                 :: "r"(s), "l"(gmem_src));
}
__device__ __forceinline__ void cp_commit() {
    asm volatile("cp.async.commit_group;\n" ::: "memory");
}

// -------------------- TF32 tensor-core GEMM ------------------------------
// C[z] = alpha * A(MxKlen slice) B(KlenxN slice), 128x128 block tile, BK=32,
// 4 warps (2x2), 64x64 warp tile -> 1:1 LDS:MMA. 2-stage cp.async pipeline.
// blockIdx.z selects a K-slice of length Klen (split-K); C is offset by
// z*M*N so partials land in separate buffers. RA/RB: round operands to tf32
// (rna) at fragment load.
#define GEMM_AS_FLOATS (128 * 36)
#define GEMM_BS_FLOATS (32 * 132)
#define GEMM_SMEM_BYTES (2 * (GEMM_AS_FLOATS + GEMM_BS_FLOATS) * 4)

template<int RA, int RB>
__global__ __launch_bounds__(128, 2) void gemm_tf32(
    const float* __restrict__ A, const float* __restrict__ B,
    float* __restrict__ C, int M, int N, int Kfull, int Klen,
    float alpha, int round_out)
{
    extern __shared__ float sm[];
    float* AsBuf = sm;                               // 2 x [128][36]
    float* BsBuf = sm + 2 * GEMM_AS_FLOATS;          // 2 x [32][132]

    const int tid  = threadIdx.x;
    const int lane = tid & 31;
    const int warp = tid >> 5;
    const int wm = warp >> 1;        // 0..1
    const int wn = warp & 1;         // 0..1
    const int bm = blockIdx.y * 128;
    const int bn = blockIdx.x * 128;
    const int qr = lane >> 2;        // 0..7
    const int qc = lane & 3;         // 0..3
    const int Kstart = blockIdx.z * Klen;

    const float* Abase = A + Kstart;
    const float* Bbase = B + (size_t)Kstart * N;
    C += (size_t)blockIdx.z * M * N;

    auto issue = [&](int kt, int stage) {
        const float* Ag = Abase + (size_t)bm * Kfull + kt * 32;
        const float* Bg = Bbase + (size_t)(kt * 32) * N + bn;
        float* Asd = AsBuf + stage * GEMM_AS_FLOATS;
        float* Bsd = BsBuf + stage * GEMM_BS_FLOATS;
#pragma unroll
        for (int i = 0; i < 8; i++) {               // A: 128x32
            int idx = tid + i * 128;
            int r = idx >> 3, k4 = (idx & 7) * 4;
            cp_async16(Asd + r * 36 + k4, Ag + (size_t)r * Kfull + k4);
        }
#pragma unroll
        for (int i = 0; i < 8; i++) {               // B: 32x128
            int idx = tid + i * 128;
            int kk = idx >> 5, n4 = (idx & 31) * 4;
            cp_async16(Bsd + kk * 132 + n4, Bg + (size_t)kk * N + n4);
        }
        cp_commit();
    };

    float acc[4][8][4];
#pragma unroll
    for (int mt = 0; mt < 4; mt++)
#pragma unroll
        for (int nt = 0; nt < 8; nt++)
#pragma unroll
            for (int i = 0; i < 4; i++) acc[mt][nt][i] = 0.f;

    const int NK = Klen / 32;
    issue(0, 0);
    for (int kt = 0; kt < NK; ++kt) {
        if (kt + 1 < NK) {
            issue(kt + 1, (kt + 1) & 1);
            asm volatile("cp.async.wait_group 1;\n" ::: "memory");
        } else {
            asm volatile("cp.async.wait_group 0;\n" ::: "memory");
        }
        __syncthreads();
        const float* Asd = AsBuf + (kt & 1) * GEMM_AS_FLOATS;
        const float* Bsd = BsBuf + (kt & 1) * GEMM_BS_FLOATS;

#pragma unroll
        for (int kk = 0; kk < 4; ++kk) {
            const int k0 = kk * 8;
            unsigned a[4][4];
#pragma unroll
            for (int mt = 0; mt < 4; ++mt) {
                int r = wm * 64 + mt * 16 + qr;
                float a0 = Asd[r * 36 + k0 + qc];
                float a1 = Asd[(r + 8) * 36 + k0 + qc];
                float a2 = Asd[r * 36 + k0 + 4 + qc];
                float a3 = Asd[(r + 8) * 36 + k0 + 4 + qc];
                if (RA) { a0 = tf32r(a0); a1 = tf32r(a1); a2 = tf32r(a2); a3 = tf32r(a3); }
                a[mt][0] = __float_as_uint(a0);
                a[mt][1] = __float_as_uint(a1);
                a[mt][2] = __float_as_uint(a2);
                a[mt][3] = __float_as_uint(a3);
            }
#pragma unroll
            for (int nt = 0; nt < 8; ++nt) {
                int c = wn * 64 + nt * 8 + qr;
                float bf0 = Bsd[(k0 + qc) * 132 + c];
                float bf1 = Bsd[(k0 + 4 + qc) * 132 + c];
                if (RB) { bf0 = tf32r(bf0); bf1 = tf32r(bf1); }
                unsigned b0 = __float_as_uint(bf0);
                unsigned b1 = __float_as_uint(bf1);
#pragma unroll
                for (int mt = 0; mt < 4; ++mt)
                    mma_tf32(acc[mt][nt], a[mt], b0, b1);
            }
        }
        __syncthreads();
    }

#pragma unroll
    for (int mt = 0; mt < 4; ++mt) {
#pragma unroll
        for (int nt = 0; nt < 8; ++nt) {
            int r = bm + wm * 64 + mt * 16 + qr;
            int c = bn + wn * 64 + nt * 8 + qc * 2;
            float v0 = alpha * acc[mt][nt][0];
            float v1 = alpha * acc[mt][nt][1];
            float v2 = alpha * acc[mt][nt][2];
            float v3 = alpha * acc[mt][nt][3];
            if (round_out) { v0 = tf32r(v0); v1 = tf32r(v1); v2 = tf32r(v2); v3 = tf32r(v3); }
            *(float2*)&C[(size_t)r * N + c] = make_float2(v0, v1);
            *(float2*)&C[(size_t)(r + 8) * N + c] = make_float2(v2, v3);
        }
    }
}

// -------------------- build K_eff / V_eff (sums split-K partials) ---------
__global__ void build_eff(const float* __restrict__ kvp,
                          float* __restrict__ keff, float* __restrict__ veff)
{
    int idx = blockIdx.x * blockDim.x + threadIdx.x;
    if (idx >= WCHUNK * DHEAD) return;
    int y = idx >> 6;
    int d = idx & 63;

    float ks = 0.f, vs = 0.f, kf = 0.f, vf = 0.f, kl = 0.f, vl = 0.f;
#pragma unroll
    for (int c = 0; c < NCHUNK; c++) {
        float kx = 0.f, vx = 0.f;
#pragma unroll
        for (int s = 0; s < NSPLIT; s++) {
            const float* row = kvp + (size_t)s * L_TOK * 2 * DHEAD
                             + (size_t)((c << 9) + y) * (2 * DHEAD);
            kx += row[d];
            vx += row[DHEAD + d];
        }
        if (c == 0)          { kf = kx; vf = vx; }
        if (c == NCHUNK - 1) { kl = kx; vl = vx; }
        ks += kx; vs += vx;
    }
    keff[(0 * WCHUNK + y) * DHEAD + d] = tf32r(ks - kl);
    keff[(1 * WCHUNK + y) * DHEAD + d] = tf32r(ks);
    keff[(2 * WCHUNK + y) * DHEAD + d] = tf32r(ks - kf);
    veff[(0 * WCHUNK + y) * DHEAD + d] = tf32r(vs - vl);
    veff[(1 * WCHUNK + y) * DHEAD + d] = tf32r(vs);
    veff[(2 * WCHUNK + y) * DHEAD + d] = tf32r(vs - vf);
}

// -------------------- TF32 flash attention --------------------------------
// 256 query rows / block (8 warps x 32 rows = 2 m-tiles/warp).
// K/V tiles of 64 keys, cp.async double-buffered. No online max (scores
// bounded, exp safe); l normalization at the end. B-fragments shared across
// both m-tiles.
#define KT 64
#define KV_STAGE_FLOATS (2 * KT * 68)          // Ks + Vs per stage
#define ATTN_SMEM_BYTES (2 * KV_STAGE_FLOATS * 4)
#define NKT (NKEY / KT)                        // 24

__global__ __launch_bounds__(256) void attn_tf32(
    const float* __restrict__ Q, const float* __restrict__ Ke,
    const float* __restrict__ Ve, float* __restrict__ O)
{
    extern __shared__ float sm[];
    const int tid  = threadIdx.x;
    const int lane = tid & 31;
    const int warp = tid >> 5;
    const int qr = lane >> 2;        // 0..7
    const int qc = lane & 3;         // 0..3
    const int qbase = blockIdx.x * 256;
    const int row0 = warp * 32 + qr; // +mt*16 per m-tile; +8 for c2/c3

    auto issueKV = [&](int kt, int stage) {
        const float* Kg = Ke + (size_t)(kt * KT) * DHEAD;
        const float* Vg = Ve + (size_t)(kt * KT) * DHEAD;
        float* Kd = sm + stage * KV_STAGE_FLOATS;
        float* Vd = Kd + KT * 68;
#pragma unroll
        for (int i = 0; i < 4; i++) {           // 64 rows x 16 float4
            int idx = tid + i * 256;
            int r = idx >> 4, c4 = (idx & 15) * 4;
            cp_async16(Kd + r * 68 + c4, Kg + (size_t)r * DHEAD + c4);
            cp_async16(Vd + r * 68 + c4, Vg + (size_t)r * DHEAD + c4);
        }
        cp_commit();
    };

    // Q fragments for both m-tiles (Q pre-rounded to tf32 by gemm epilogue)
    unsigned aq[2][8][4];
#pragma unroll
    for (int mt = 0; mt < 2; mt++) {
        const float* q0 = Q + (size_t)(qbase + row0 + mt * 16) * DHEAD;
        const float* q8 = q0 + 8 * DHEAD;
#pragma unroll
        for (int kk = 0; kk < 8; kk++) {
            int c = kk * 8 + qc;
            aq[mt][kk][0] = __float_as_uint(q0[c]);
            aq[mt][kk][1] = __float_as_uint(q8[c]);
            aq[mt][kk][2] = __float_as_uint(q0[c + 4]);
            aq[mt][kk][3] = __float_as_uint(q8[c + 4]);
        }
    }

    float oacc[2][8][4];
#pragma unroll
    for (int mt = 0; mt < 2; mt++)
#pragma unroll
        for (int n = 0; n < 8; n++)
#pragma unroll
            for (int i = 0; i < 4; i++) oacc[mt][n][i] = 0.f;
    float lp0[2] = {0.f, 0.f};   // per-lane partial row sums (rows r / r+8)
    float lp1[2] = {0.f, 0.f};

    const int base = lane & ~3;
    const int s0 = base + (qc >> 1);
    const int s1 = s0 + 2;
    const bool odd = (qc & 1);

    issueKV(0, 0);
    for (int kt = 0; kt < NKT; ++kt) {
        if (kt + 1 < NKT) {
            issueKV(kt + 1, (kt + 1) & 1);
            asm volatile("cp.async.wait_group 1;\n" ::: "memory");
        } else {
            asm volatile("cp.async.wait_group 0;\n" ::: "memory");
        }
        __syncthreads();
        const float* Ks = sm + (kt & 1) * KV_STAGE_FLOATS;
        const float* Vs = Ks + KT * 68;

        // ---- S = Q K^T for both m-tiles, B-frags loaded once ----
        float p[2][8][4];
#pragma unroll
        for (int mt = 0; mt < 2; mt++)
#pragma unroll
            for (int nt = 0; nt < 8; nt++)
#pragma unroll
                for (int i = 0; i < 4; i++) p[mt][nt][i] = 0.f;

#pragma unroll
        for (int kk = 0; kk < 8; ++kk) {
            const int k0 = kk * 8;
#pragma unroll
            for (int nt = 0; nt < 8; ++nt) {
                int keyr = nt * 8 + qr;
                unsigned b0 = __float_as_uint(Ks[keyr * 68 + k0 + qc]);
                unsigned b1 = __float_as_uint(Ks[keyr * 68 + k0 + 4 + qc]);
                mma_tf32(p[0][nt], aq[0][kk], b0, b1);
                mma_tf32(p[1][nt], aq[1][kk], b0, b1);
            }
        }

        // ---- exp (no max subtraction) + l partials ----
#pragma unroll
        for (int mt = 0; mt < 2; mt++)
#pragma unroll
            for (int nt = 0; nt < 8; nt++) {
                p[mt][nt][0] = __expf(p[mt][nt][0]);
                p[mt][nt][1] = __expf(p[mt][nt][1]);
                p[mt][nt][2] = __expf(p[mt][nt][2]);
                p[mt][nt][3] = __expf(p[mt][nt][3]);
                lp0[mt] += p[mt][nt][0] + p[mt][nt][1];
                lp1[mt] += p[mt][nt][2] + p[mt][nt][3];
            }

        // ---- O += P V : shuffle C-frag -> A-frag; V B-frags shared ------
#pragma unroll
        for (int j = 0; j < 8; ++j) {        // PV k-tiles == S n-tiles
            unsigned pa[2][4];
#pragma unroll
            for (int mt = 0; mt < 2; mt++) {
                float x0 = __shfl_sync(0xffffffffu, p[mt][j][0], s0);
                float x1 = __shfl_sync(0xffffffffu, p[mt][j][1], s0);
                float x2 = __shfl_sync(0xffffffffu, p[mt][j][2], s0);
                float x3 = __shfl_sync(0xffffffffu, p[mt][j][3], s0);
                float y0 = __shfl_sync(0xffffffffu, p[mt][j][0], s1);
                float y1 = __shfl_sync(0xffffffffu, p[mt][j][1], s1);
                float y2 = __shfl_sync(0xffffffffu, p[mt][j][2], s1);
                float y3 = __shfl_sync(0xffffffffu, p[mt][j][3], s1);
                pa[mt][0] = __float_as_uint(tf32r(odd ? x1 : x0)); // (r,   c)
                pa[mt][1] = __float_as_uint(tf32r(odd ? x3 : x2)); // (r+8, c)
                pa[mt][2] = __float_as_uint(tf32r(odd ? y1 : y0)); // (r,   c+4)
                pa[mt][3] = __float_as_uint(tf32r(odd ? y3 : y2)); // (r+8, c+4)
            }
            const int kr = j * 8 + qc;
#pragma unroll
            for (int n = 0; n < 8; ++n) {
                unsigned b0 = __float_as_uint(Vs[kr * 68 + n * 8 + qr]);
                unsigned b1 = __float_as_uint(Vs[(kr + 4) * 68 + n * 8 + qr]);
                mma_tf32(oacc[0][n], pa[0], b0, b1);
                mma_tf32(oacc[1][n], pa[1], b0, b1);
            }
        }
        __syncthreads();
    }

    // ---- finalize: reduce l across quad lanes, O / l, round to tf32 -----
#pragma unroll
    for (int mt = 0; mt < 2; mt++) {
        float l0 = lp0[mt], l1 = lp1[mt];
        l0 += __shfl_xor_sync(0xffffffffu, l0, 1);
        l0 += __shfl_xor_sync(0xffffffffu, l0, 2);
        l1 += __shfl_xor_sync(0xffffffffu, l1, 1);
        l1 += __shfl_xor_sync(0xffffffffu, l1, 2);
        float inv0 = 1.f / l0, inv1 = 1.f / l1;
        const int r = qbase + row0 + mt * 16;
#pragma unroll
        for (int n = 0; n < 8; ++n) {
            int c = n * 8 + qc * 2;
            float2 v0 = make_float2(tf32r(oacc[mt][n][0] * inv0),
                                    tf32r(oacc[mt][n][1] * inv0));
            float2 v1 = make_float2(tf32r(oacc[mt][n][2] * inv1),
                                    tf32r(oacc[mt][n][3] * inv1));
            *(float2*)&O[(size_t)r * DHEAD + c] = v0;
            *(float2*)&O[(size_t)(r + 8) * DHEAD + c] = v1;
        }
    }
}

// -------------------- launch --------------------
extern "C" void kernel_launch(void* const* d_in, const int* in_sizes, int n_in,
                              void* d_out, int out_size)
{
    const float* q   = (const float*)d_in[0];
    const float* kv  = (const float*)d_in[1];
    const float* Wq  = (const float*)d_in[2];
    const float* Wkv = (const float*)d_in[3];
    const float* Wc  = (const float*)d_in[4];
    float* out = (float*)d_out;

    float *qp, *kvp, *keff, *veff, *ctx;
    cudaGetSymbolAddress((void**)&qp,   g_qp);
    cudaGetSymbolAddress((void**)&kvp,  g_kvp);
    cudaGetSymbolAddress((void**)&keff, g_keff);
    cudaGetSymbolAddress((void**)&veff, g_veff);
    cudaGetSymbolAddress((void**)&ctx,  g_ctx);

    cudaFuncSetAttribute(gemm_tf32<1,1>,
                         cudaFuncAttributeMaxDynamicSharedMemorySize,
                         GEMM_SMEM_BYTES);
    cudaFuncSetAttribute(gemm_tf32<0,1>,
                         cudaFuncAttributeMaxDynamicSharedMemorySize,
                         GEMM_SMEM_BYTES);
    cudaFuncSetAttribute(attn_tf32,
                         cudaFuncAttributeMaxDynamicSharedMemorySize,
                         ATTN_SMEM_BYTES);

    // kvp partials = kv @ Wkv, split-K=4 (4096 x 128 x 256 each)
    gemm_tf32<1,1><<<dim3(1, 32, NSPLIT), 128, GEMM_SMEM_BYTES>>>(
        kv, Wkv, kvp, L_TOK, 2 * DHEAD, DMODEL, DMODEL / NSPLIT, 1.0f, 0);
    // K_eff / V_eff chunk sums over splits (tf32-rounded)
    build_eff<<<(WCHUNK * DHEAD + 255) / 256, 256>>>(kvp, keff, veff);
    // qp = (q @ Wq) / 8  (4096 x 1024 x 1024), rounded output for attention
    gemm_tf32<1,1><<<dim3(8, 32, 1), 128, GEMM_SMEM_BYTES>>>(
        q, Wq, qp, L_TOK, DMODEL, DMODEL, DMODEL, 0.125f, 1);
    // attention: Q[65536,64] vs shared K/V[1536,64], 256 rows/block
    attn_tf32<<<NQROW / 256, 256, ATTN_SMEM_BYTES>>>(qp, keff, veff, ctx);
    // out = ctx @ Wc  (ctx already tf32; round only Wc at frag load)
    gemm_tf32<0,1><<<dim3(8, 32, 1), 128, GEMM_SMEM_BYTES>>>(
        ctx, Wc, out, L_TOK, DMODEL, DMODEL, DMODEL, 1.0f, 0);
}

// round 10
// speedup vs baseline: 8.8235x; 1.4275x over previous
#include <cuda_runtime.h>
#include <cuda_fp16.h>
#include <cuda_bf16.h>
#include <math.h>

// Problem constants (B=1, L=4096, DM=1024, NH=16, DH=64, w=512, C=8)
#define L_TOK   4096
#define DMODEL  1024
#define DHEAD   64
#define WCHUNK  512
#define NCHUNK  8
#define NKEY    1536                 // 3*w effective keys (z-sum collapses chunks)
#define NQROW   65536                // L * NH query rows of dim 64
#define NSPLIT  4                    // split-K factor for the kvp GEMM

#define LOG2E   1.4426950408889634f

// -------------------- scratch (no cudaMalloc allowed) --------------------
__device__ __half g_qph[NQROW * DHEAD];               // 8 MB fp16 (pre-scaled by log2e)
__device__ float  g_kvp[NSPLIT * L_TOK * 2 * DHEAD];  // split-K partials
__device__ __half g_keff[NKEY * DHEAD];               // fp16 [key][dim]
__device__ __half g_vt  [DHEAD * NKEY];               // fp16 transposed [dim][key]
__device__ float  g_ctx [NQROW * DHEAD];              // 16 MB (tf32-rounded)

// -------------------- helpers --------------------
__device__ __forceinline__ float tf32r(float x) {
    unsigned u;
    asm("cvt.rna.tf32.f32 %0, %1;" : "=r"(u) : "f"(x));
    return __uint_as_float(u);
}
__device__ __forceinline__ float ex2f(float x) {
    float y;
    asm("ex2.approx.ftz.f32 %0, %1;" : "=f"(y) : "f"(x));
    return y;
}
__device__ __forceinline__ unsigned h2_as_u32(__half2 h) {
    return *reinterpret_cast<unsigned*>(&h);
}

__device__ __forceinline__ void mma_tf32(float* c, const unsigned* a,
                                         unsigned b0, unsigned b1) {
    asm volatile(
        "mma.sync.aligned.m16n8k8.row.col.f32.tf32.tf32.f32 "
        "{%0,%1,%2,%3},{%4,%5,%6,%7},{%8,%9},{%0,%1,%2,%3};"
        : "+f"(c[0]), "+f"(c[1]), "+f"(c[2]), "+f"(c[3])
        : "r"(a[0]), "r"(a[1]), "r"(a[2]), "r"(a[3]), "r"(b0), "r"(b1));
}

__device__ __forceinline__ void mma_f16(float* c, const unsigned* a,
                                        unsigned b0, unsigned b1) {
    asm volatile(
        "mma.sync.aligned.m16n8k16.row.col.f32.f16.f16.f32 "
        "{%0,%1,%2,%3},{%4,%5,%6,%7},{%8,%9},{%0,%1,%2,%3};"
        : "+f"(c[0]), "+f"(c[1]), "+f"(c[2]), "+f"(c[3])
        : "r"(a[0]), "r"(a[1]), "r"(a[2]), "r"(a[3]), "r"(b0), "r"(b1));
}

__device__ __forceinline__ void cp_async16(void* smem_dst, const void* gmem_src) {
    unsigned s = (unsigned)__cvta_generic_to_shared(smem_dst);
    asm volatile("cp.async.ca.shared.global [%0], [%1], 16;\n"
                 :: "r"(s), "l"(gmem_src));
}
__device__ __forceinline__ void cp_commit() {
    asm volatile("cp.async.commit_group;\n" ::: "memory");
}

// -------------------- TF32 tensor-core GEMM ------------------------------
// 128x128 block tile, BK=32, 4 warps (2x2), 64x64 warp tile, 2-stage cp.async.
// blockIdx.z selects a K-slice (split-K); C offset by z*M*N.
// RA/RB: round operands to tf32 at fragment load.
// OUT: 0 = plain f32, 1 = tf32-rounded f32, 2 = fp16 (__half).
#define GEMM_AS_FLOATS (128 * 36)
#define GEMM_BS_FLOATS (32 * 132)
#define GEMM_SMEM_BYTES (2 * (GEMM_AS_FLOATS + GEMM_BS_FLOATS) * 4)

template<int RA, int RB, int OUT>
__global__ __launch_bounds__(128, 2) void gemm_tf32(
    const float* __restrict__ A, const float* __restrict__ B,
    float* __restrict__ C, int M, int N, int Kfull, int Klen, float alpha)
{
    extern __shared__ float sm[];
    float* AsBuf = sm;                               // 2 x [128][36]
    float* BsBuf = sm + 2 * GEMM_AS_FLOATS;          // 2 x [32][132]

    const int tid  = threadIdx.x;
    const int lane = tid & 31;
    const int warp = tid >> 5;
    const int wm = warp >> 1;        // 0..1
    const int wn = warp & 1;         // 0..1
    const int bm = blockIdx.y * 128;
    const int bn = blockIdx.x * 128;
    const int qr = lane >> 2;        // 0..7
    const int qc = lane & 3;         // 0..3
    const int Kstart = blockIdx.z * Klen;

    const float* Abase = A + Kstart;
    const float* Bbase = B + (size_t)Kstart * N;
    C += (size_t)blockIdx.z * M * N;

    auto issue = [&](int kt, int stage) {
        const float* Ag = Abase + (size_t)bm * Kfull + kt * 32;
        const float* Bg = Bbase + (size_t)(kt * 32) * N + bn;
        float* Asd = AsBuf + stage * GEMM_AS_FLOATS;
        float* Bsd = BsBuf + stage * GEMM_BS_FLOATS;
#pragma unroll
        for (int i = 0; i < 8; i++) {               // A: 128x32
            int idx = tid + i * 128;
            int r = idx >> 3, k4 = (idx & 7) * 4;
            cp_async16(Asd + r * 36 + k4, Ag + (size_t)r * Kfull + k4);
        }
#pragma unroll
        for (int i = 0; i < 8; i++) {               // B: 32x128
            int idx = tid + i * 128;
            int kk = idx >> 5, n4 = (idx & 31) * 4;
            cp_async16(Bsd + kk * 132 + n4, Bg + (size_t)kk * N + n4);
        }
        cp_commit();
    };

    float acc[4][8][4];
#pragma unroll
    for (int mt = 0; mt < 4; mt++)
#pragma unroll
        for (int nt = 0; nt < 8; nt++)
#pragma unroll
            for (int i = 0; i < 4; i++) acc[mt][nt][i] = 0.f;

    const int NK = Klen / 32;
    issue(0, 0);
    for (int kt = 0; kt < NK; ++kt) {
        if (kt + 1 < NK) {
            issue(kt + 1, (kt + 1) & 1);
            asm volatile("cp.async.wait_group 1;\n" ::: "memory");
        } else {
            asm volatile("cp.async.wait_group 0;\n" ::: "memory");
        }
        __syncthreads();
        const float* Asd = AsBuf + (kt & 1) * GEMM_AS_FLOATS;
        const float* Bsd = BsBuf + (kt & 1) * GEMM_BS_FLOATS;

#pragma unroll
        for (int kk = 0; kk < 4; ++kk) {
            const int k0 = kk * 8;
            unsigned a[4][4];
#pragma unroll
            for (int mt = 0; mt < 4; ++mt) {
                int r = wm * 64 + mt * 16 + qr;
                float a0 = Asd[r * 36 + k0 + qc];
                float a1 = Asd[(r + 8) * 36 + k0 + qc];
                float a2 = Asd[r * 36 + k0 + 4 + qc];
                float a3 = Asd[(r + 8) * 36 + k0 + 4 + qc];
                if (RA) { a0 = tf32r(a0); a1 = tf32r(a1); a2 = tf32r(a2); a3 = tf32r(a3); }
                a[mt][0] = __float_as_uint(a0);
                a[mt][1] = __float_as_uint(a1);
                a[mt][2] = __float_as_uint(a2);
                a[mt][3] = __float_as_uint(a3);
            }
#pragma unroll
            for (int nt = 0; nt < 8; ++nt) {
                int c = wn * 64 + nt * 8 + qr;
                float bf0 = Bsd[(k0 + qc) * 132 + c];
                float bf1 = Bsd[(k0 + 4 + qc) * 132 + c];
                if (RB) { bf0 = tf32r(bf0); bf1 = tf32r(bf1); }
                unsigned b0 = __float_as_uint(bf0);
                unsigned b1 = __float_as_uint(bf1);
#pragma unroll
                for (int mt = 0; mt < 4; ++mt)
                    mma_tf32(acc[mt][nt], a[mt], b0, b1);
            }
        }
        __syncthreads();
    }

#pragma unroll
    for (int mt = 0; mt < 4; ++mt) {
#pragma unroll
        for (int nt = 0; nt < 8; ++nt) {
            int r = bm + wm * 64 + mt * 16 + qr;
            int c = bn + wn * 64 + nt * 8 + qc * 2;
            float v0 = alpha * acc[mt][nt][0];
            float v1 = alpha * acc[mt][nt][1];
            float v2 = alpha * acc[mt][nt][2];
            float v3 = alpha * acc[mt][nt][3];
            if (OUT == 2) {
                __half* Ch = (__half*)C;
                *(__half2*)&Ch[(size_t)r * N + c] = __floats2half2_rn(v0, v1);
                *(__half2*)&Ch[(size_t)(r + 8) * N + c] = __floats2half2_rn(v2, v3);
            } else {
                if (OUT == 1) { v0 = tf32r(v0); v1 = tf32r(v1); v2 = tf32r(v2); v3 = tf32r(v3); }
                *(float2*)&C[(size_t)r * N + c] = make_float2(v0, v1);
                *(float2*)&C[(size_t)(r + 8) * N + c] = make_float2(v2, v3);
            }
        }
    }
}

// -------------------- build K_eff / V_eff^T (fp16, sums split-K partials) -
__global__ void build_eff(const float* __restrict__ kvp,
                          __half* __restrict__ keff, __half* __restrict__ vt)
{
    int idx = blockIdx.x * blockDim.x + threadIdx.x;
    if (idx >= WCHUNK * DHEAD) return;
    int y = idx >> 6;
    int d = idx & 63;

    float ks = 0.f, vs = 0.f, kf = 0.f, vf = 0.f, kl = 0.f, vl = 0.f;
#pragma unroll
    for (int c = 0; c < NCHUNK; c++) {
        float kx = 0.f, vx = 0.f;
#pragma unroll
        for (int s = 0; s < NSPLIT; s++) {
            const float* row = kvp + (size_t)s * L_TOK * 2 * DHEAD
                             + (size_t)((c << 9) + y) * (2 * DHEAD);
            kx += row[d];
            vx += row[DHEAD + d];
        }
        if (c == 0)          { kf = kx; vf = vx; }
        if (c == NCHUNK - 1) { kl = kx; vl = vx; }
        ks += kx; vs += vx;
    }
    // K_eff fp16 [e*512+y][d]; V_eff^T fp16 [d][e*512+y]
    keff[(0 * WCHUNK + y) * DHEAD + d] = __float2half_rn(ks - kl);
    keff[(1 * WCHUNK + y) * DHEAD + d] = __float2half_rn(ks);
    keff[(2 * WCHUNK + y) * DHEAD + d] = __float2half_rn(ks - kf);
    vt[(size_t)d * NKEY + 0 * WCHUNK + y] = __float2half_rn(vs - vl);
    vt[(size_t)d * NKEY + 1 * WCHUNK + y] = __float2half_rn(vs);
    vt[(size_t)d * NKEY + 2 * WCHUNK + y] = __float2half_rn(vs - vf);
}

// -------------------- FP16 flash attention --------------------------------
// 128 query rows / block (4 warps x 32 rows = 2 m-tiles of 16). Grid 512,
// 2 CTAs/SM. K/V tiles of 64 keys in fp16 smem (stride 72 halves,
// conflict-free), cp.async double-buffered. No online max (scores bounded);
// Q pre-scaled by log2e so exp == single ex2.approx. S C-frags convert
// directly into PV A-frags (m16n8k16 layout identity) -- zero shuffles.
#define SH 72                                   // smem stride in halves
#define AT_STAGE_H (2 * 64 * SH)                // K + Vt per stage (halves)
#define ATTN_SMEM_BYTES (2 * AT_STAGE_H * 2)    // 36864 B
#define NKT (NKEY / 64)                         // 24

__global__ __launch_bounds__(128, 2) void attn_fp16(
    const __half* __restrict__ Q, const __half* __restrict__ Ke,
    const __half* __restrict__ Vt, float* __restrict__ O)
{
    extern __shared__ __half smh[];
    const int tid  = threadIdx.x;
    const int lane = tid & 31;
    const int warp = tid >> 5;       // 0..3
    const int qr = lane >> 2;        // 0..7
    const int qc = lane & 3;         // 0..3
    const int qbase = blockIdx.x * 128;
    const int row0 = warp * 32 + qr; // +mt*16; +8 for c2/c3

    auto issueKV = [&](int kt, int stage) {
        const __half* Kg = Ke + (size_t)(kt * 64) * DHEAD;   // [key][64]
        const __half* Vg = Vt + kt * 64;                     // [dim][NKEY]
        __half* Kd = smh + stage * AT_STAGE_H;
        __half* Vd = Kd + 64 * SH;
#pragma unroll
        for (int i = 0; i < 4; i++) {          // 64 rows x 8 chunks each
            int idx = tid + i * 128;
            int r = idx >> 3, c8 = (idx & 7) * 8;
            cp_async16(Kd + r * SH + c8, Kg + r * DHEAD + c8);
            cp_async16(Vd + r * SH + c8, Vg + (size_t)r * NKEY + c8);
        }
        cp_commit();
    };

    // Q A-fragments for both m-tiles: 4 k16-chunks, 4 b32 each (fp16 pairs)
    unsigned aq[2][4][4];
#pragma unroll
    for (int mt = 0; mt < 2; mt++) {
        const __half* q0 = Q + (size_t)(qbase + row0 + mt * 16) * DHEAD;
        const __half* q8 = q0 + 8 * DHEAD;
#pragma unroll
        for (int kk = 0; kk < 4; kk++) {
            int c = kk * 16 + 2 * qc;
            aq[mt][kk][0] = *(const unsigned*)(q0 + c);
            aq[mt][kk][1] = *(const unsigned*)(q8 + c);
            aq[mt][kk][2] = *(const unsigned*)(q0 + c + 8);
            aq[mt][kk][3] = *(const unsigned*)(q8 + c + 8);
        }
    }

    float oacc[2][8][4];
#pragma unroll
    for (int mt = 0; mt < 2; mt++)
#pragma unroll
        for (int n = 0; n < 8; n++)
#pragma unroll
            for (int i = 0; i < 4; i++) oacc[mt][n][i] = 0.f;
    float lp0[2] = {0.f, 0.f};   // per-lane partial row sums (rows r / r+8)
    float lp1[2] = {0.f, 0.f};

    issueKV(0, 0);
    for (int kt = 0; kt < NKT; ++kt) {
        if (kt + 1 < NKT) {
            issueKV(kt + 1, (kt + 1) & 1);
            asm volatile("cp.async.wait_group 1;\n" ::: "memory");
        } else {
            asm volatile("cp.async.wait_group 0;\n" ::: "memory");
        }
        __syncthreads();
        const __half* Ks = smh + (kt & 1) * AT_STAGE_H;
        const __half* Vs = Ks + 64 * SH;

        // ---- S = Q K^T (32 rows x 64 keys per warp), fp16 mma k16 ----
        float p[2][8][4];
#pragma unroll
        for (int mt = 0; mt < 2; mt++)
#pragma unroll
            for (int nt = 0; nt < 8; nt++)
#pragma unroll
                for (int i = 0; i < 4; i++) p[mt][nt][i] = 0.f;

#pragma unroll
        for (int kk = 0; kk < 4; ++kk) {
#pragma unroll
            for (int nt = 0; nt < 8; ++nt) {
                const __half* kr = Ks + (nt * 8 + qr) * SH + kk * 16 + 2 * qc;
                unsigned b0 = *(const unsigned*)(kr);
                unsigned b1 = *(const unsigned*)(kr + 8);
                mma_f16(p[0][nt], aq[0][kk], b0, b1);
                mma_f16(p[1][nt], aq[1][kk], b0, b1);
            }
        }

        // ---- exp2 (Q pre-scaled by log2e; no max needed) + l partials ----
        // ---- and pack C-frags straight into PV A-frags (no shuffles) ----
        unsigned ph[2][8][2];
#pragma unroll
        for (int mt = 0; mt < 2; mt++)
#pragma unroll
            for (int nt = 0; nt < 8; nt++) {
                float e0 = ex2f(p[mt][nt][0]);
                float e1 = ex2f(p[mt][nt][1]);
                float e2 = ex2f(p[mt][nt][2]);
                float e3 = ex2f(p[mt][nt][3]);
                lp0[mt] += e0 + e1;
                lp1[mt] += e2 + e3;
                ph[mt][nt][0] = h2_as_u32(__floats2half2_rn(e0, e1)); // row r
                ph[mt][nt][1] = h2_as_u32(__floats2half2_rn(e2, e3)); // row r+8
            }

        // ---- O += P V : A-frag = {ph[2j][0..1], ph[2j+1][0..1]} ----
#pragma unroll
        for (int j = 0; j < 4; ++j) {
#pragma unroll
            for (int n = 0; n < 8; ++n) {
                const __half* vr = Vs + (n * 8 + qr) * SH + j * 16 + 2 * qc;
                unsigned b0 = *(const unsigned*)(vr);
                unsigned b1 = *(const unsigned*)(vr + 8);
                mma_f16(oacc[0][n], &ph[0][2 * j][0], b0, b1);
                mma_f16(oacc[1][n], &ph[1][2 * j][0], b0, b1);
            }
        }
        __syncthreads();
    }

    // ---- finalize: reduce l across quad lanes, O / l, round to tf32 -----
#pragma unroll
    for (int mt = 0; mt < 2; mt++) {
        float l0 = lp0[mt], l1 = lp1[mt];
        l0 += __shfl_xor_sync(0xffffffffu, l0, 1);
        l0 += __shfl_xor_sync(0xffffffffu, l0, 2);
        l1 += __shfl_xor_sync(0xffffffffu, l1, 1);
        l1 += __shfl_xor_sync(0xffffffffu, l1, 2);
        float inv0 = 1.f / l0, inv1 = 1.f / l1;
        const int r = qbase + row0 + mt * 16;
#pragma unroll
        for (int n = 0; n < 8; ++n) {
            int c = n * 8 + qc * 2;
            float2 v0 = make_float2(tf32r(oacc[mt][n][0] * inv0),
                                    tf32r(oacc[mt][n][1] * inv0));
            float2 v1 = make_float2(tf32r(oacc[mt][n][2] * inv1),
                                    tf32r(oacc[mt][n][3] * inv1));
            *(float2*)&O[(size_t)r * DHEAD + c] = v0;
            *(float2*)&O[(size_t)(r + 8) * DHEAD + c] = v1;
        }
    }
}

// -------------------- launch --------------------
extern "C" void kernel_launch(void* const* d_in, const int* in_sizes, int n_in,
                              void* d_out, int out_size)
{
    const float* q   = (const float*)d_in[0];
    const float* kv  = (const float*)d_in[1];
    const float* Wq  = (const float*)d_in[2];
    const float* Wkv = (const float*)d_in[3];
    const float* Wc  = (const float*)d_in[4];
    float* out = (float*)d_out;

    __half *qph, *keff, *vt;
    float *kvp, *ctx;
    cudaGetSymbolAddress((void**)&qph,  g_qph);
    cudaGetSymbolAddress((void**)&kvp,  g_kvp);
    cudaGetSymbolAddress((void**)&keff, g_keff);
    cudaGetSymbolAddress((void**)&vt,   g_vt);
    cudaGetSymbolAddress((void**)&ctx,  g_ctx);

    cudaFuncSetAttribute(gemm_tf32<1,1,0>,
                         cudaFuncAttributeMaxDynamicSharedMemorySize,
                         GEMM_SMEM_BYTES);
    cudaFuncSetAttribute(gemm_tf32<1,1,2>,
                         cudaFuncAttributeMaxDynamicSharedMemorySize,
                         GEMM_SMEM_BYTES);
    cudaFuncSetAttribute(gemm_tf32<0,1,0>,
                         cudaFuncAttributeMaxDynamicSharedMemorySize,
                         GEMM_SMEM_BYTES);
    cudaFuncSetAttribute(attn_fp16,
                         cudaFuncAttributeMaxDynamicSharedMemorySize,
                         ATTN_SMEM_BYTES);

    // kvp partials = kv @ Wkv, split-K=4 (4096 x 128 x 256 each)
    gemm_tf32<1,1,0><<<dim3(1, 32, NSPLIT), 128, GEMM_SMEM_BYTES>>>(
        kv, Wkv, kvp, L_TOK, 2 * DHEAD, DMODEL, DMODEL / NSPLIT, 1.0f);
    // K_eff fp16 + V_eff^T fp16 (chunk sums over splits)
    build_eff<<<(WCHUNK * DHEAD + 255) / 256, 256>>>(kvp, keff, vt);
    // qp = (q @ Wq) * log2e / 8, fp16 output (exp becomes bare ex2)
    gemm_tf32<1,1,2><<<dim3(8, 32, 1), 128, GEMM_SMEM_BYTES>>>(
        q, Wq, (float*)qph, L_TOK, DMODEL, DMODEL, DMODEL, 0.125f * LOG2E);
    // attention: Q[65536,64] fp16 vs shared K/V[1536,64] fp16
    attn_fp16<<<NQROW / 128, 128, ATTN_SMEM_BYTES>>>(qph, keff, vt, ctx);
    // out = ctx @ Wc  (ctx tf32-rounded by attention epilogue)
    gemm_tf32<0,1,0><<<dim3(8, 32, 1), 128, GEMM_SMEM_BYTES>>>(
        ctx, Wc, out, L_TOK, DMODEL, DMODEL, DMODEL, 1.0f);
}

// round 11
// speedup vs baseline: 11.4325x; 1.2957x over previous
#include <cuda_runtime.h>
#include <cuda_fp16.h>
#include <cuda_bf16.h>
#include <math.h>

// Problem constants (B=1, L=4096, DM=1024, NH=16, DH=64, w=512, C=8)
#define L_TOK   4096
#define DMODEL  1024
#define DHEAD   64
#define WCHUNK  512
#define NCHUNK  8
#define NKEY    1536                 // 3*w effective keys (z-sum collapses chunks)
#define NQROW   65536                // L * NH query rows of dim 64
#define NSPLIT  4                    // split-K factor for the kvp GEMM

#define LOG2E   1.4426950408889634f

// -------------------- scratch (no cudaMalloc allowed) --------------------
__device__ __half g_qh  [L_TOK * DMODEL];             // fp16 q
__device__ __half g_kvh [L_TOK * DMODEL];             // fp16 kv
__device__ __half g_WqT [DMODEL * DMODEL];            // fp16 Wq^T  [N][K]
__device__ __half g_WkvT[2 * DHEAD * DMODEL];         // fp16 Wkv^T [N][K]
__device__ __half g_WcT [DMODEL * DMODEL];            // fp16 Wc^T  [N][K]
__device__ __half g_qph [NQROW * DHEAD];              // qp fp16 (pre-scaled log2e)
__device__ float  g_kvp [NSPLIT * L_TOK * 2 * DHEAD]; // split-K partials
__device__ __half g_keff[NKEY * DHEAD];               // fp16 [key][dim]
__device__ __half g_vt  [DHEAD * NKEY];               // fp16 transposed [dim][key]
__device__ __half g_ctxh[NQROW * DHEAD];              // attention output fp16

// -------------------- helpers --------------------
__device__ __forceinline__ float ex2f(float x) {
    float y;
    asm("ex2.approx.ftz.f32 %0, %1;" : "=f"(y) : "f"(x));
    return y;
}
__device__ __forceinline__ unsigned h2_as_u32(__half2 h) {
    return *reinterpret_cast<unsigned*>(&h);
}

__device__ __forceinline__ void mma_f16(float* c, const unsigned* a,
                                        unsigned b0, unsigned b1) {
    asm volatile(
        "mma.sync.aligned.m16n8k16.row.col.f32.f16.f16.f32 "
        "{%0,%1,%2,%3},{%4,%5,%6,%7},{%8,%9},{%0,%1,%2,%3};"
        : "+f"(c[0]), "+f"(c[1]), "+f"(c[2]), "+f"(c[3])
        : "r"(a[0]), "r"(a[1]), "r"(a[2]), "r"(a[3]), "r"(b0), "r"(b1));
}

__device__ __forceinline__ void cp_async16(void* smem_dst, const void* gmem_src) {
    unsigned s = (unsigned)__cvta_generic_to_shared(smem_dst);
    asm volatile("cp.async.ca.shared.global [%0], [%1], 16;\n"
                 :: "r"(s), "l"(gmem_src));
}
__device__ __forceinline__ void cp_commit() {
    asm volatile("cp.async.commit_group;\n" ::: "memory");
}

// -------------------- prepass: fp32 -> fp16 elementwise -------------------
__global__ void to_half4(const float* __restrict__ in, __half* __restrict__ out,
                         int n)
{
    int i = (blockIdx.x * blockDim.x + threadIdx.x) * 4;
    if (i < n) {
        float4 v = *(const float4*)(in + i);
        *(__half2*)(out + i)     = __floats2half2_rn(v.x, v.y);
        *(__half2*)(out + i + 2) = __floats2half2_rn(v.z, v.w);
    }
}

// -------------------- prepass: transpose + fp16 (W [R][C] -> WT [C][R]) ---
__global__ void transpose_h(const float* __restrict__ W, __half* __restrict__ WT,
                            int R, int C)
{
    __shared__ float t[32][33];
    int cb = blockIdx.x * 32, rb = blockIdx.y * 32;
    int tx = threadIdx.x, ty = threadIdx.y;     // 32 x 8
#pragma unroll
    for (int j = 0; j < 32; j += 8)
        t[ty + j][tx] = W[(size_t)(rb + ty + j) * C + cb + tx];
    __syncthreads();
#pragma unroll
    for (int j = 0; j < 32; j += 8)
        WT[(size_t)(cb + ty + j) * R + rb + tx] = __float2half_rn(t[tx][ty + j]);
}

// -------------------- FP16 tensor-core GEMM ------------------------------
// C = alpha * A(M x Klen) B^T-slice, A fp16 [M][Kfull] row-major,
// B fp16 [N][Kfull] (pre-transposed weights). 128x128 block tile, BK=64,
// 4 warps (2x2), 64x64 warp tile. Stride-72 smem, conflict-free b32 frag
// loads. 2-stage cp.async. blockIdx.z = split-K slice; C offset z*M*N.
// OUT: 0 = fp32 C, 2 = fp16 C.
#define SA 72
#define GF16_STAGE (128 * SA)                 // halves per operand stage
#define GF16_SMEM_BYTES (4 * GF16_STAGE * 2)  // 73728 B

template<int OUT>
__global__ __launch_bounds__(128, 2) void gemm_f16(
    const __half* __restrict__ A, const __half* __restrict__ B,
    void* __restrict__ Cv, int M, int N, int Kfull, int Klen, float alpha)
{
    extern __shared__ __half smh[];
    __half* AsBuf = smh;                      // 2 x [128][SA]
    __half* BsBuf = smh + 2 * GF16_STAGE;     // 2 x [128][SA]

    const int tid  = threadIdx.x;
    const int lane = tid & 31;
    const int warp = tid >> 5;
    const int wm = warp >> 1;        // 0..1
    const int wn = warp & 1;         // 0..1
    const int bm = blockIdx.y * 128;
    const int bn = blockIdx.x * 128;
    const int qr = lane >> 2;        // 0..7
    const int qc = lane & 3;         // 0..3
    const int Kstart = blockIdx.z * Klen;

    const __half* Ab = A + (size_t)bm * Kfull + Kstart;
    const __half* Bb = B + (size_t)bn * Kfull + Kstart;

    auto issue = [&](int kt, int stage) {
        const __half* Ag = Ab + kt * 64;
        const __half* Bg = Bb + kt * 64;
        __half* Asd = AsBuf + stage * GF16_STAGE;
        __half* Bsd = BsBuf + stage * GF16_STAGE;
#pragma unroll
        for (int i = 0; i < 8; i++) {          // 128 rows x 8 x 16B each op
            int idx = tid + i * 128;
            int r = idx >> 3, c8 = (idx & 7) * 8;
            cp_async16(Asd + r * SA + c8, Ag + (size_t)r * Kfull + c8);
            cp_async16(Bsd + r * SA + c8, Bg + (size_t)r * Kfull + c8);
        }
        cp_commit();
    };

    float acc[4][8][4];
#pragma unroll
    for (int mt = 0; mt < 4; mt++)
#pragma unroll
        for (int nt = 0; nt < 8; nt++)
#pragma unroll
            for (int i = 0; i < 4; i++) acc[mt][nt][i] = 0.f;

    const int NK = Klen / 64;
    issue(0, 0);
    for (int kt = 0; kt < NK; ++kt) {
        if (kt + 1 < NK) {
            issue(kt + 1, (kt + 1) & 1);
            asm volatile("cp.async.wait_group 1;\n" ::: "memory");
        } else {
            asm volatile("cp.async.wait_group 0;\n" ::: "memory");
        }
        __syncthreads();
        const __half* As = AsBuf + (kt & 1) * GF16_STAGE;
        const __half* Bs = BsBuf + (kt & 1) * GF16_STAGE;

#pragma unroll
        for (int ck = 0; ck < 4; ++ck) {       // 4 k16 chunks per BK=64
            const int k0 = ck * 16 + 2 * qc;
            unsigned a[4][4];
#pragma unroll
            for (int mt = 0; mt < 4; ++mt) {
                const __half* ar = As + (wm * 64 + mt * 16 + qr) * SA + k0;
                a[mt][0] = *(const unsigned*)(ar);
                a[mt][1] = *(const unsigned*)(ar + 8 * SA);
                a[mt][2] = *(const unsigned*)(ar + 8);
                a[mt][3] = *(const unsigned*)(ar + 8 * SA + 8);
            }
#pragma unroll
            for (int nt = 0; nt < 8; ++nt) {
                const __half* br = Bs + (wn * 64 + nt * 8 + qr) * SA + k0;
                unsigned b0 = *(const unsigned*)(br);
                unsigned b1 = *(const unsigned*)(br + 8);
#pragma unroll
                for (int mt = 0; mt < 4; ++mt)
                    mma_f16(acc[mt][nt], a[mt], b0, b1);
            }
        }
        __syncthreads();
    }

#pragma unroll
    for (int mt = 0; mt < 4; ++mt) {
#pragma unroll
        for (int nt = 0; nt < 8; ++nt) {
            int r = bm + wm * 64 + mt * 16 + qr;
            int c = bn + wn * 64 + nt * 8 + qc * 2;
            float v0 = alpha * acc[mt][nt][0];
            float v1 = alpha * acc[mt][nt][1];
            float v2 = alpha * acc[mt][nt][2];
            float v3 = alpha * acc[mt][nt][3];
            if (OUT == 2) {
                __half* Ch = (__half*)Cv + (size_t)blockIdx.z * M * N;
                *(__half2*)&Ch[(size_t)r * N + c] = __floats2half2_rn(v0, v1);
                *(__half2*)&Ch[(size_t)(r + 8) * N + c] = __floats2half2_rn(v2, v3);
            } else {
                float* Cf = (float*)Cv + (size_t)blockIdx.z * M * N;
                *(float2*)&Cf[(size_t)r * N + c] = make_float2(v0, v1);
                *(float2*)&Cf[(size_t)(r + 8) * N + c] = make_float2(v2, v3);
            }
        }
    }
}

// -------------------- build K_eff / V_eff^T (fp16, sums split-K partials) -
__global__ void build_eff(const float* __restrict__ kvp,
                          __half* __restrict__ keff, __half* __restrict__ vt)
{
    int idx = blockIdx.x * blockDim.x + threadIdx.x;
    if (idx >= WCHUNK * DHEAD) return;
    int y = idx >> 6;
    int d = idx & 63;

    float ks = 0.f, vs = 0.f, kf = 0.f, vf = 0.f, kl = 0.f, vl = 0.f;
#pragma unroll
    for (int c = 0; c < NCHUNK; c++) {
        float kx = 0.f, vx = 0.f;
#pragma unroll
        for (int s = 0; s < NSPLIT; s++) {
            const float* row = kvp + (size_t)s * L_TOK * 2 * DHEAD
                             + (size_t)((c << 9) + y) * (2 * DHEAD);
            kx += row[d];
            vx += row[DHEAD + d];
        }
        if (c == 0)          { kf = kx; vf = vx; }
        if (c == NCHUNK - 1) { kl = kx; vl = vx; }
        ks += kx; vs += vx;
    }
    // K_eff fp16 [e*512+y][d]; V_eff^T fp16 [d][e*512+y]
    keff[(0 * WCHUNK + y) * DHEAD + d] = __float2half_rn(ks - kl);
    keff[(1 * WCHUNK + y) * DHEAD + d] = __float2half_rn(ks);
    keff[(2 * WCHUNK + y) * DHEAD + d] = __float2half_rn(ks - kf);
    vt[(size_t)d * NKEY + 0 * WCHUNK + y] = __float2half_rn(vs - vl);
    vt[(size_t)d * NKEY + 1 * WCHUNK + y] = __float2half_rn(vs);
    vt[(size_t)d * NKEY + 2 * WCHUNK + y] = __float2half_rn(vs - vf);
}

// -------------------- FP16 flash attention --------------------------------
// 128 query rows / block (4 warps x 32 rows = 2 m-tiles of 16). Grid 512,
// 2 CTAs/SM. K/V tiles of 64 keys in fp16 smem (stride 72, conflict-free),
// cp.async double-buffered. No online max (scores bounded); Q pre-scaled by
// log2e so exp == bare ex2.approx. S C-frags feed PV A-frags directly
// (m16n8k16 layout identity). Output fp16 (feeds the Wc fp16 GEMM).
#define SH 72                                   // smem stride in halves
#define AT_STAGE_H (2 * 64 * SH)                // K + Vt per stage (halves)
#define ATTN_SMEM_BYTES (2 * AT_STAGE_H * 2)    // 36864 B
#define NKT (NKEY / 64)                         // 24

__global__ __launch_bounds__(128, 2) void attn_fp16(
    const __half* __restrict__ Q, const __half* __restrict__ Ke,
    const __half* __restrict__ Vt, __half* __restrict__ O)
{
    extern __shared__ __half smh[];
    const int tid  = threadIdx.x;
    const int lane = tid & 31;
    const int warp = tid >> 5;       // 0..3
    const int qr = lane >> 2;        // 0..7
    const int qc = lane & 3;         // 0..3
    const int qbase = blockIdx.x * 128;
    const int row0 = warp * 32 + qr; // +mt*16; +8 for c2/c3

    auto issueKV = [&](int kt, int stage) {
        const __half* Kg = Ke + (size_t)(kt * 64) * DHEAD;   // [key][64]
        const __half* Vg = Vt + kt * 64;                     // [dim][NKEY]
        __half* Kd = smh + stage * AT_STAGE_H;
        __half* Vd = Kd + 64 * SH;
#pragma unroll
        for (int i = 0; i < 4; i++) {          // 64 rows x 8 chunks each
            int idx = tid + i * 128;
            int r = idx >> 3, c8 = (idx & 7) * 8;
            cp_async16(Kd + r * SH + c8, Kg + r * DHEAD + c8);
            cp_async16(Vd + r * SH + c8, Vg + (size_t)r * NKEY + c8);
        }
        cp_commit();
    };

    // Q A-fragments for both m-tiles: 4 k16-chunks, 4 b32 each (fp16 pairs)
    unsigned aq[2][4][4];
#pragma unroll
    for (int mt = 0; mt < 2; mt++) {
        const __half* q0 = Q + (size_t)(qbase + row0 + mt * 16) * DHEAD;
        const __half* q8 = q0 + 8 * DHEAD;
#pragma unroll
        for (int kk = 0; kk < 4; kk++) {
            int c = kk * 16 + 2 * qc;
            aq[mt][kk][0] = *(const unsigned*)(q0 + c);
            aq[mt][kk][1] = *(const unsigned*)(q8 + c);
            aq[mt][kk][2] = *(const unsigned*)(q0 + c + 8);
            aq[mt][kk][3] = *(const unsigned*)(q8 + c + 8);
        }
    }

    float oacc[2][8][4];
#pragma unroll
    for (int mt = 0; mt < 2; mt++)
#pragma unroll
        for (int n = 0; n < 8; n++)
#pragma unroll
            for (int i = 0; i < 4; i++) oacc[mt][n][i] = 0.f;
    float lp0[2] = {0.f, 0.f};   // per-lane partial row sums (rows r / r+8)
    float lp1[2] = {0.f, 0.f};

    issueKV(0, 0);
    for (int kt = 0; kt < NKT; ++kt) {
        if (kt + 1 < NKT) {
            issueKV(kt + 1, (kt + 1) & 1);
            asm volatile("cp.async.wait_group 1;\n" ::: "memory");
        } else {
            asm volatile("cp.async.wait_group 0;\n" ::: "memory");
        }
        __syncthreads();
        const __half* Ks = smh + (kt & 1) * AT_STAGE_H;
        const __half* Vs = Ks + 64 * SH;

        // ---- S = Q K^T (32 rows x 64 keys per warp), fp16 mma k16 ----
        float p[2][8][4];
#pragma unroll
        for (int mt = 0; mt < 2; mt++)
#pragma unroll
            for (int nt = 0; nt < 8; nt++)
#pragma unroll
                for (int i = 0; i < 4; i++) p[mt][nt][i] = 0.f;

#pragma unroll
        for (int kk = 0; kk < 4; ++kk) {
#pragma unroll
            for (int nt = 0; nt < 8; ++nt) {
                const __half* kr = Ks + (nt * 8 + qr) * SH + kk * 16 + 2 * qc;
                unsigned b0 = *(const unsigned*)(kr);
                unsigned b1 = *(const unsigned*)(kr + 8);
                mma_f16(p[0][nt], aq[0][kk], b0, b1);
                mma_f16(p[1][nt], aq[1][kk], b0, b1);
            }
        }

        // ---- exp2 (Q pre-scaled by log2e) + l partials, pack to A-frags --
        unsigned ph[2][8][2];
#pragma unroll
        for (int mt = 0; mt < 2; mt++)
#pragma unroll
            for (int nt = 0; nt < 8; nt++) {
                float e0 = ex2f(p[mt][nt][0]);
                float e1 = ex2f(p[mt][nt][1]);
                float e2 = ex2f(p[mt][nt][2]);
                float e3 = ex2f(p[mt][nt][3]);
                lp0[mt] += e0 + e1;
                lp1[mt] += e2 + e3;
                ph[mt][nt][0] = h2_as_u32(__floats2half2_rn(e0, e1)); // row r
                ph[mt][nt][1] = h2_as_u32(__floats2half2_rn(e2, e3)); // row r+8
            }

        // ---- O += P V : A-frag = {ph[2j][0..1], ph[2j+1][0..1]} ----
#pragma unroll
        for (int j = 0; j < 4; ++j) {
#pragma unroll
            for (int n = 0; n < 8; ++n) {
                const __half* vr = Vs + (n * 8 + qr) * SH + j * 16 + 2 * qc;
                unsigned b0 = *(const unsigned*)(vr);
                unsigned b1 = *(const unsigned*)(vr + 8);
                mma_f16(oacc[0][n], &ph[0][2 * j][0], b0, b1);
                mma_f16(oacc[1][n], &ph[1][2 * j][0], b0, b1);
            }
        }
        __syncthreads();
    }

    // ---- finalize: reduce l across quad lanes, O / l, emit fp16 ---------
#pragma unroll
    for (int mt = 0; mt < 2; mt++) {
        float l0 = lp0[mt], l1 = lp1[mt];
        l0 += __shfl_xor_sync(0xffffffffu, l0, 1);
        l0 += __shfl_xor_sync(0xffffffffu, l0, 2);
        l1 += __shfl_xor_sync(0xffffffffu, l1, 1);
        l1 += __shfl_xor_sync(0xffffffffu, l1, 2);
        float inv0 = 1.f / l0, inv1 = 1.f / l1;
        const int r = qbase + row0 + mt * 16;
#pragma unroll
        for (int n = 0; n < 8; ++n) {
            int c = n * 8 + qc * 2;
            *(__half2*)&O[(size_t)r * DHEAD + c] =
                __floats2half2_rn(oacc[mt][n][0] * inv0, oacc[mt][n][1] * inv0);
            *(__half2*)&O[(size_t)(r + 8) * DHEAD + c] =
                __floats2half2_rn(oacc[mt][n][2] * inv1, oacc[mt][n][3] * inv1);
        }
    }
}

// -------------------- launch --------------------
extern "C" void kernel_launch(void* const* d_in, const int* in_sizes, int n_in,
                              void* d_out, int out_size)
{
    const float* q   = (const float*)d_in[0];
    const float* kv  = (const float*)d_in[1];
    const float* Wq  = (const float*)d_in[2];
    const float* Wkv = (const float*)d_in[3];
    const float* Wc  = (const float*)d_in[4];
    float* out = (float*)d_out;

    __half *qh, *kvh, *WqT, *WkvT, *WcT, *qph, *keff, *vt, *ctxh;
    float *kvp;
    cudaGetSymbolAddress((void**)&qh,   g_qh);
    cudaGetSymbolAddress((void**)&kvh,  g_kvh);
    cudaGetSymbolAddress((void**)&WqT,  g_WqT);
    cudaGetSymbolAddress((void**)&WkvT, g_WkvT);
    cudaGetSymbolAddress((void**)&WcT,  g_WcT);
    cudaGetSymbolAddress((void**)&qph,  g_qph);
    cudaGetSymbolAddress((void**)&kvp,  g_kvp);
    cudaGetSymbolAddress((void**)&keff, g_keff);
    cudaGetSymbolAddress((void**)&vt,   g_vt);
    cudaGetSymbolAddress((void**)&ctxh, g_ctxh);

    cudaFuncSetAttribute(gemm_f16<0>,
                         cudaFuncAttributeMaxDynamicSharedMemorySize,
                         GF16_SMEM_BYTES);
    cudaFuncSetAttribute(gemm_f16<2>,
                         cudaFuncAttributeMaxDynamicSharedMemorySize,
                         GF16_SMEM_BYTES);
    cudaFuncSetAttribute(attn_fp16,
                         cudaFuncAttributeMaxDynamicSharedMemorySize,
                         ATTN_SMEM_BYTES);

    // prepass: activations to fp16; weights transposed+fp16
    to_half4<<<4096, 256>>>(q,  qh,  L_TOK * DMODEL);
    to_half4<<<4096, 256>>>(kv, kvh, L_TOK * DMODEL);
    transpose_h<<<dim3(32, 32), dim3(32, 8)>>>(Wq,  WqT,  DMODEL, DMODEL);
    transpose_h<<<dim3(4,  32), dim3(32, 8)>>>(Wkv, WkvT, DMODEL, 2 * DHEAD);
    transpose_h<<<dim3(32, 32), dim3(32, 8)>>>(Wc,  WcT,  DMODEL, DMODEL);

    // kvp partials = kv @ Wkv, split-K=4 (4096 x 128 x 256 each)
    gemm_f16<0><<<dim3(1, 32, NSPLIT), 128, GF16_SMEM_BYTES>>>(
        kvh, WkvT, kvp, L_TOK, 2 * DHEAD, DMODEL, DMODEL / NSPLIT, 1.0f);
    // K_eff fp16 + V_eff^T fp16 (chunk sums over splits)
    build_eff<<<(WCHUNK * DHEAD + 255) / 256, 256>>>(kvp, keff, vt);
    // qp = (q @ Wq) * log2e / 8, fp16 output (exp becomes bare ex2)
    gemm_f16<2><<<dim3(8, 32, 1), 128, GF16_SMEM_BYTES>>>(
        qh, WqT, qph, L_TOK, DMODEL, DMODEL, DMODEL, 0.125f * LOG2E);
    // attention: Q[65536,64] fp16 vs shared K/V[1536,64] fp16 -> fp16 ctx
    attn_fp16<<<NQROW / 128, 128, ATTN_SMEM_BYTES>>>(qph, keff, vt, ctxh);
    // out = ctx @ Wc (fp16 x fp16 -> fp32)
    gemm_f16<0><<<dim3(8, 32, 1), 128, GF16_SMEM_BYTES>>>(
        ctxh, WcT, out, L_TOK, DMODEL, DMODEL, DMODEL, 1.0f);
}